// round 9
// baseline (speedup 1.0000x reference)
#include <cuda_runtime.h>
#include <cuda_fp16.h>
#include <cstdint>
#include <math.h>

// ---------------- problem constants ----------------
#define HW     16384      // 128*128
#define WIMG   128
#define C_IN   192
#define C3     576        // 3*C_IN
#define NB     8
#define HEADS  8
#define HD     24

// ---------------- scratch ----------------
__device__ __half g_y  [16][C3 * HW];
__device__ __half g_qkv[16][C3 * HW];
__device__ float  g_S  [2][NB][HEADS][HD * HD];
__device__ float  g_css[16][C3];
__device__ float  g_M  [2][NB][C_IN * C_IN];

// ---------------- K0: zero accumulators ----------------
__global__ void k0_zero() {
    int idx = blockIdx.x * 256 + threadIdx.x;
    const int nS = 2 * NB * HEADS * HD * HD;
    const int nC = 16 * C3;
    if (idx < nS) (&g_S[0][0][0][0])[idx] = 0.f;
    if (idx < nC) (&g_css[0][0])[idx] = 0.f;
}

// ---------------- fp16 / mma helpers ----------------
__device__ __forceinline__ uint32_t pack2(float a, float b) {
    __half2 h = __floats2half2_rn(a, b);
    return *(uint32_t*)&h;
}
__device__ __forceinline__ uint32_t interleave_lo(uint32_t x, uint32_t y) {
    uint32_t r;
    asm("prmt.b32 %0, %1, %2, 0x5410;" : "=r"(r) : "r"(x), "r"(y));
    return r;
}
__device__ __forceinline__ uint32_t interleave_hi(uint32_t x, uint32_t y) {
    uint32_t r;
    asm("prmt.b32 %0, %1, %2, 0x7632;" : "=r"(r) : "r"(x), "r"(y));
    return r;
}
__device__ __forceinline__ void mma_16x8x16(float* c, const uint32_t* a, const uint32_t* b) {
    asm volatile(
        "mma.sync.aligned.m16n8k16.row.col.f32.f16.f16.f32 "
        "{%0,%1,%2,%3}, {%4,%5,%6,%7}, {%8,%9}, {%0,%1,%2,%3};"
        : "+f"(c[0]), "+f"(c[1]), "+f"(c[2]), "+f"(c[3])
        : "r"(a[0]), "r"(a[1]), "r"(a[2]), "r"(a[3]), "r"(b[0]), "r"(b[1]));
}
__device__ __forceinline__ void ldmx4(uint32_t* r, uint32_t addr) {
    asm volatile("ldmatrix.sync.aligned.m8n8.x4.shared.b16 {%0,%1,%2,%3}, [%4];"
        : "=r"(r[0]), "=r"(r[1]), "=r"(r[2]), "=r"(r[3]) : "r"(addr));
}
__device__ __forceinline__ void ldmx2(uint32_t* r, uint32_t addr) {
    asm volatile("ldmatrix.sync.aligned.m8n8.x2.shared.b16 {%0,%1}, [%2];"
        : "=r"(r[0]), "=r"(r[1]) : "r"(addr));
}
__device__ __forceinline__ uint32_t sh_addr(const void* p) {
    return (uint32_t)__cvta_generic_to_shared(p);
}

// ---------------- fp16 mma GEMM: C[m0:m0+192, n0:n0+128] ----------------
// 512 threads, 16 warps (4M x 4N), warp tile 48x32. BK=32, double-buffered, 6 chunks.
template<bool B_HALF, bool C_HALF>
__device__ __forceinline__ void gemm_mma_192x128(
    const float* __restrict__ A, const void* __restrict__ Bv, void* __restrict__ Cv,
    int m0, int n0)
{
    __shared__ uint32_t As[2][192][20];   // [m][k2]
    __shared__ uint32_t Bs[2][16][136];   // [k2][n] packing (k,k+1)

    const int tid  = threadIdx.x;
    const int wid  = tid >> 5;
    const int lane = tid & 31;
    const int warp_m = wid & 3;           // 0..3 -> 48 rows
    const int warp_n = wid >> 2;          // 0..3 -> 32 cols
    const int lr = lane >> 2;
    const int lc = lane & 3;

    // staging indices (512 threads)
    const int ar = tid >> 3;              // 0..63 (+64,+128)
    const int aq = tid & 7;               // k quad
    const int bk2 = tid >> 5;             // 0..15
    const int bn4 = (tid & 31) * 4;       // 0..124

    const float* Ap = A + (size_t)(m0 + ar) * 192 + aq * 4;
    const float*  Bpf = B_HALF ? nullptr : ((const float*)Bv + (size_t)(2 * bk2) * HW + n0 + bn4);
    const __half* Bph = B_HALF ? ((const __half*)Bv + (size_t)(2 * bk2) * HW + n0 + bn4) : nullptr;

    const int lg = lane >> 3;
    const int lrow = lane & 7;
    const uint32_t a_lane_off = (uint32_t)((((lg & 1) << 3) + lrow) * 20 + ((lg >> 1) << 2)) * 4;
    const uint32_t As0 = sh_addr(&As[0][0][0]);
    const uint32_t As1 = sh_addr(&As[1][0][0]);

    uint32_t au[3][2];
    uint32_t bu[4];

    auto loadB = [&](int ch) {
        if (B_HALF) {
            const __half* bp = Bph + (size_t)(ch * 32) * HW;
            uint2 r0 = *(const uint2*)bp;
            uint2 r1 = *(const uint2*)(bp + HW);
            bu[0] = interleave_lo(r0.x, r1.x);
            bu[1] = interleave_hi(r0.x, r1.x);
            bu[2] = interleave_lo(r0.y, r1.y);
            bu[3] = interleave_hi(r0.y, r1.y);
        } else {
            const float* bp = Bpf + (size_t)(ch * 32) * HW;
            float4 r0 = *(const float4*)bp;
            float4 r1 = *(const float4*)(bp + HW);
            bu[0] = pack2(r0.x, r1.x);
            bu[1] = pack2(r0.y, r1.y);
            bu[2] = pack2(r0.z, r1.z);
            bu[3] = pack2(r0.w, r1.w);
        }
    };
    auto loadA = [&](int ch) {
#pragma unroll
        for (int it = 0; it < 3; it++) {
            float4 v = *(const float4*)(Ap + ch * 32 + (size_t)it * 64 * 192);
            au[it][0] = pack2(v.x, v.y);
            au[it][1] = pack2(v.z, v.w);
        }
    };
    auto stage = [&](int nb) {
#pragma unroll
        for (int it = 0; it < 3; it++) {
            As[nb][ar + it * 64][aq * 2]     = au[it][0];
            As[nb][ar + it * 64][aq * 2 + 1] = au[it][1];
        }
        *(uint4*)&Bs[nb][bk2][bn4] = *(uint4*)bu;
    };

    loadA(0); loadB(0);
    stage(0);
    __syncthreads();

    float acc[3][4][4];
#pragma unroll
    for (int i = 0; i < 3; i++)
#pragma unroll
        for (int j = 0; j < 4; j++)
#pragma unroll
            for (int q = 0; q < 4; q++) acc[i][j][q] = 0.f;

    int buf = 0;
    for (int ch = 0; ch < 6; ch++) {
        if (ch < 5) { loadA(ch + 1); loadB(ch + 1); }
        const uint32_t Asb = (buf ? As1 : As0) + a_lane_off;
#pragma unroll
        for (int kst = 0; kst < 2; kst++) {
            const int k2 = kst * 8;
            uint32_t afr[3][4];
#pragma unroll
            for (int mt = 0; mt < 3; mt++)
                ldmx4(afr[mt], Asb + (uint32_t)(((warp_m * 48 + mt * 16) * 20 + k2) * 4));
#pragma unroll
            for (int nt = 0; nt < 4; nt++) {
                int nn = warp_n * 32 + nt * 8 + lr;
                uint32_t bfr[2];
                bfr[0] = Bs[buf][k2 + lc][nn];
                bfr[1] = Bs[buf][k2 + 4 + lc][nn];
#pragma unroll
                for (int mt = 0; mt < 3; mt++)
                    mma_16x8x16(acc[mt][nt], afr[mt], bfr);
            }
        }
        if (ch < 5) {
            int nb = buf ^ 1;
            stage(nb);
            __syncthreads();
            buf = nb;
        }
    }

#pragma unroll
    for (int mt = 0; mt < 3; mt++) {
        int row = m0 + warp_m * 48 + mt * 16 + lr;
#pragma unroll
        for (int nt = 0; nt < 4; nt++) {
            int col = n0 + warp_n * 32 + nt * 8 + lc * 2;
            if (C_HALF) {
                __half* Ch = (__half*)Cv;
                *(uint32_t*)(Ch + (size_t)row * HW + col)       = pack2(acc[mt][nt][0], acc[mt][nt][1]);
                *(uint32_t*)(Ch + (size_t)(row + 8) * HW + col) = pack2(acc[mt][nt][2], acc[mt][nt][3]);
            } else {
                float* Cf = (float*)Cv;
                *(float2*)(Cf + (size_t)row * HW + col)       = make_float2(acc[mt][nt][0], acc[mt][nt][1]);
                *(float2*)(Cf + (size_t)(row + 8) * HW + col) = make_float2(acc[mt][nt][2], acc[mt][nt][3]);
            }
        }
    }
}

// ---------------- K1: 1x1 qkv conv ----------------
__global__ void __launch_bounds__(512, 1)
k1_qkv(const float* __restrict__ rgb, const float* __restrict__ ir,
       const float* __restrict__ wqkv)
{
    int z = blockIdx.z, s = z >> 3, b = z & 7;
    const float* x = (s ? ir : rgb) + (size_t)b * C_IN * HW;
    gemm_mma_192x128<false, true>(wqkv, x, g_y[z], blockIdx.y * 192, blockIdx.x * 128);
}

// ---------------- K5: out = M @ V ----------------
__global__ void __launch_bounds__(512, 1)
k5_out(float* __restrict__ out)
{
    int z = blockIdx.z;
    const float* A = g_M[z >> 3][z & 7];
    const __half* V = g_qkv[z] + (size_t)(2 * C_IN) * HW;
    float* C = out + (size_t)z * C_IN * HW;
    gemm_mma_192x128<true, false>(A, V, C, 0, blockIdx.x * 128);
}

// ---------------- K2: depthwise 3x3 SAME, 8 px/thread + sumsq ----------------
__global__ void k2_dw(const float* __restrict__ wdw)
{
    int z  = blockIdx.z;
    int ch = blockIdx.y;
    int n  = blockIdx.x * 2048 + threadIdx.x * 8;
    const __half* yin = g_y[z]  + (size_t)ch * HW;
    __half*       out = g_qkv[z] + (size_t)ch * HW;

    const float* w = wdw + ch * 9;
    float wr[3][3];
#pragma unroll
    for (int i = 0; i < 9; i++) wr[i / 3][i % 3] = w[i];

    int yy = n >> 7, xx = n & 127;
    bool xm = (xx > 0), xp = (xx < 120);

    float f[3][10];
#pragma unroll
    for (int r = 0; r < 3; r++) {
        int ry = yy + r - 1;
        if (ry < 0 || ry >= WIMG) {
#pragma unroll
            for (int i = 0; i < 10; i++) f[r][i] = 0.f;
            continue;
        }
        const __half* row = yin + (size_t)ry * WIMG;
        uint4 v = *(const uint4*)&row[xx];
        float2 p0 = __half22float2(*(__half2*)&v.x);
        float2 p1 = __half22float2(*(__half2*)&v.y);
        float2 p2 = __half22float2(*(__half2*)&v.z);
        float2 p3 = __half22float2(*(__half2*)&v.w);
        f[r][1] = p0.x; f[r][2] = p0.y; f[r][3] = p1.x; f[r][4] = p1.y;
        f[r][5] = p2.x; f[r][6] = p2.y; f[r][7] = p3.x; f[r][8] = p3.y;
        f[r][0] = xm ? __half2float(row[xx - 1]) : 0.f;
        f[r][9] = xp ? __half2float(row[xx + 8]) : 0.f;
    }

    float o[8];
    float ss = 0.f;
#pragma unroll
    for (int i = 0; i < 8; i++) {
        float acc = 0.f;
#pragma unroll
        for (int r = 0; r < 3; r++)
            acc += wr[r][0] * f[r][i] + wr[r][1] * f[r][i + 1] + wr[r][2] * f[r][i + 2];
        o[i] = acc;
        ss += acc * acc;
    }
    uint4 ov;
    ov.x = pack2(o[0], o[1]);
    ov.y = pack2(o[2], o[3]);
    ov.z = pack2(o[4], o[5]);
    ov.w = pack2(o[6], o[7]);
    *(uint4*)&out[n] = ov;

#pragma unroll
    for (int off = 16; off; off >>= 1) ss += __shfl_xor_sync(0xFFFFFFFFu, ss, off);
    if ((threadIdx.x & 31) == 0) atomicAdd(&g_css[z][ch], ss);
}

// ---------------- K3: channel Gram via tensor cores + ldmatrix ----------------
__global__ void __launch_bounds__(256)
k3_gram()
{
    __shared__ __align__(16) char smraw[16896 + 12672];  // qsm[32][132] + ksm[24][132] half2
    __half2 (*qsm)[132] = reinterpret_cast<__half2(*)[132]>(smraw);
    __half2 (*ksm)[132] = reinterpret_cast<__half2(*)[132]>(smraw + 16896);
    float* red = reinterpret_cast<float*>(smraw);

    int t  = blockIdx.z;
    int bh = blockIdx.y;
    int b = bh >> 3, h = bh & 7;
    int n0 = blockIdx.x * 2048;

    int qs = (t == 0) ? 1 : 0;
    int kstream = 1 - qs;
    const __half* qb = g_qkv[qs * 8 + b]      + (size_t)(h * HD) * HW + n0;
    const __half* kb = g_qkv[kstream * 8 + b] + (size_t)(C_IN + h * HD) * HW + n0;

    const int tid  = threadIdx.x;
    const int wid  = tid >> 5;
    const int lane = tid & 31;
    const int kw = wid * 16;

    const int lg = lane >> 3;
    const int lrow = lane & 7;
    const uint32_t q_lane_off = (uint32_t)((((lg & 1) << 3) + lrow) * 132 + ((lg >> 1) << 2)) * 4;
    const uint32_t k_lane_off = (uint32_t)(((lane & 15) & 7) * 132 + (((lane & 15) >> 3) << 2)) * 4;
    const uint32_t qbase = sh_addr(&qsm[0][0]);
    const uint32_t kbase = sh_addr(&ksm[0][0]);

    float acc[2][3][4];
#pragma unroll
    for (int i = 0; i < 2; i++)
#pragma unroll
        for (int j = 0; j < 3; j++)
#pragma unroll
            for (int q = 0; q < 4; q++) acc[i][j][q] = 0.f;

    for (int c0 = 0; c0 < 2048; c0 += 256) {
        __syncthreads();
        for (int i = tid; i < 1536; i += 256) {
            int arr = (i >= 768);
            int li  = arr ? (i - 768) : i;
            int row = li >> 5;
            int v8  = (li & 31) * 8;
            const __half* src = arr ? kb : qb;
            uint4 v = *(const uint4*)&src[(size_t)row * HW + c0 + v8];
            if (arr) *(uint4*)&ksm[row][v8 >> 1] = v;
            else     *(uint4*)&qsm[row][v8 >> 1] = v;
        }
        __syncthreads();
#pragma unroll
        for (int kst = 0; kst < 2; kst++) {
            const int ko = kw + kst * 8;
            uint32_t afr[2][4];
#pragma unroll
            for (int mt = 0; mt < 2; mt++)
                ldmx4(afr[mt], qbase + q_lane_off + (uint32_t)((mt * 16 * 132 + ko) * 4));
#pragma unroll
            for (int nt = 0; nt < 3; nt++) {
                uint32_t bfr[2];
                ldmx2(bfr, kbase + k_lane_off + (uint32_t)((nt * 8 * 132 + ko) * 4));
#pragma unroll
                for (int mt = 0; mt < 2; mt++)
                    mma_16x8x16(acc[mt][nt], afr[mt], bfr);
            }
        }
    }
    __syncthreads();

    const int lr = lane >> 2;
    const int lc = lane & 3;
    float* rw = red + wid * 576;
#pragma unroll
    for (int mt = 0; mt < 2; mt++) {
        int r0 = mt * 16 + lr;
#pragma unroll
        for (int nt = 0; nt < 3; nt++) {
            int cc = nt * 8 + lc * 2;
            rw[r0 * 24 + cc]     = acc[mt][nt][0];
            rw[r0 * 24 + cc + 1] = acc[mt][nt][1];
            if (mt == 0) {
                rw[(r0 + 8) * 24 + cc]     = acc[mt][nt][2];
                rw[(r0 + 8) * 24 + cc + 1] = acc[mt][nt][3];
            }
        }
    }
    __syncthreads();

    float* Sp = &g_S[t][b][h][0];
    for (int i = tid; i < 576; i += 256) {
        float s = 0.f;
#pragma unroll
        for (int w = 0; w < 8; w++) s += red[w * 576 + i];
        atomicAdd(&Sp[i], s);
    }
}

// ---------------- K4: scale + softmax + M = wproj @ blockdiag(attn) ----------------
__global__ void k4_softmax_M(const float* __restrict__ wproj,
                             const float* __restrict__ temp)
{
    int t = blockIdx.x >> 3, b = blockIdx.x & 7;
    int qs = (t == 0) ? 1 : 0;
    int kstream = 1 - qs;
    __shared__ float attn[C_IN][HD + 1];
    __shared__ float invq[C_IN], invk[C_IN];

    int tid = threadIdx.x;                 // 192 ; tid = h*HD + c
    {
        invq[tid] = 1.f / fmaxf(sqrtf(g_css[qs * 8 + b][tid]), 1e-12f);
        invk[tid] = 1.f / fmaxf(sqrtf(g_css[kstream * 8 + b][C_IN + tid]), 1e-12f);
    }
    __syncthreads();
    {
        int h = tid / HD, c = tid % HD;
        float tp = temp[h];
        float iq = invq[tid];
        float row[HD];
        float mx = -1e30f;
#pragma unroll
        for (int d = 0; d < HD; d++) {
            float v = g_S[t][b][h][c * HD + d] * iq * invk[h * HD + d] * tp;
            row[d] = v;
            mx = fmaxf(mx, v);
        }
        float sum = 0.f;
#pragma unroll
        for (int d = 0; d < HD; d++) { row[d] = expf(row[d] - mx); sum += row[d]; }
        float inv = 1.f / sum;
#pragma unroll
        for (int d = 0; d < HD; d++) attn[tid][d] = row[d] * inv;
    }
    __syncthreads();

    int o = tid;
    const float* wp = wproj + (size_t)o * C_IN;
    float* Mrow = &g_M[t][b][(size_t)o * C_IN];
    for (int h = 0; h < HEADS; h++) {
        float wreg[HD];
#pragma unroll
        for (int i = 0; i < HD; i++) wreg[i] = wp[h * HD + i];
#pragma unroll
        for (int j = 0; j < HD; j++) {
            float s = 0.f;
#pragma unroll
            for (int i = 0; i < HD; i++) s += wreg[i] * attn[h * HD + i][j];
            Mrow[h * HD + j] = s;
        }
    }
}

// ---------------- launch ----------------
extern "C" void kernel_launch(void* const* d_in, const int* in_sizes, int n_in,
                              void* d_out, int out_size)
{
    const float* rgb   = (const float*)d_in[0];
    const float* ir    = (const float*)d_in[1];
    const float* wqkv  = (const float*)d_in[2];
    const float* wdw   = (const float*)d_in[3];
    const float* wproj = (const float*)d_in[4];
    const float* temp  = (const float*)d_in[5];
    float* out = (float*)d_out;

    k0_zero<<<288, 256>>>();

    dim3 g1(HW / 128, 3, 16);     // m0: 0,192,384
    k1_qkv<<<g1, 512>>>(rgb, ir, wqkv);

    dim3 g2(HW / 2048, C3, 16);
    k2_dw<<<g2, 256>>>(wdw);

    dim3 g3(8, NB * HEADS, 2);    // K-slices of 2048
    k3_gram<<<g3, 256>>>();

    k4_softmax_M<<<16, 192>>>(wproj, temp);

    dim3 g5(HW / 128, 1, 16);     // single m pass (192 rows)
    k5_out<<<g5, 512>>>(out);
}

// round 10
// speedup vs baseline: 1.0217x; 1.0217x over previous
#include <cuda_runtime.h>
#include <cuda_fp16.h>
#include <cstdint>
#include <math.h>

// ---------------- problem constants ----------------
#define HW     16384      // 128*128
#define WIMG   128
#define C_IN   192
#define C3     576        // 3*C_IN
#define NB     8
#define HEADS  8
#define HD     24

// ---------------- scratch ----------------
__device__ __half g_y  [16][C3 * HW];
__device__ __half g_qkv[16][C3 * HW];
__device__ float  g_S  [2][NB][HEADS][HD * HD];
__device__ float  g_css[16][C3];
__device__ float  g_M  [2][NB][C_IN * C_IN];

// ---------------- K0: zero accumulators ----------------
__global__ void k0_zero() {
    int idx = blockIdx.x * 256 + threadIdx.x;
    const int nS = 2 * NB * HEADS * HD * HD;
    const int nC = 16 * C3;
    if (idx < nS) (&g_S[0][0][0][0])[idx] = 0.f;
    if (idx < nC) (&g_css[0][0])[idx] = 0.f;
}

// no-op shims so ncu's fixed skip-count lands on k1_qkv
__global__ void k_nop1() {}
__global__ void k_nop2() {}

// ---------------- fp16 / mma helpers ----------------
__device__ __forceinline__ uint32_t pack2(float a, float b) {
    __half2 h = __floats2half2_rn(a, b);
    return *(uint32_t*)&h;
}
__device__ __forceinline__ uint32_t interleave_lo(uint32_t x, uint32_t y) {
    uint32_t r;
    asm("prmt.b32 %0, %1, %2, 0x5410;" : "=r"(r) : "r"(x), "r"(y));
    return r;
}
__device__ __forceinline__ uint32_t interleave_hi(uint32_t x, uint32_t y) {
    uint32_t r;
    asm("prmt.b32 %0, %1, %2, 0x7632;" : "=r"(r) : "r"(x), "r"(y));
    return r;
}
__device__ __forceinline__ void mma_16x8x16(float* c, const uint32_t* a, const uint32_t* b) {
    asm volatile(
        "mma.sync.aligned.m16n8k16.row.col.f32.f16.f16.f32 "
        "{%0,%1,%2,%3}, {%4,%5,%6,%7}, {%8,%9}, {%0,%1,%2,%3};"
        : "+f"(c[0]), "+f"(c[1]), "+f"(c[2]), "+f"(c[3])
        : "r"(a[0]), "r"(a[1]), "r"(a[2]), "r"(a[3]), "r"(b[0]), "r"(b[1]));
}
__device__ __forceinline__ void ldmx4(uint32_t* r, uint32_t addr) {
    asm volatile("ldmatrix.sync.aligned.m8n8.x4.shared.b16 {%0,%1,%2,%3}, [%4];"
        : "=r"(r[0]), "=r"(r[1]), "=r"(r[2]), "=r"(r[3]) : "r"(addr));
}
__device__ __forceinline__ void ldmx2(uint32_t* r, uint32_t addr) {
    asm volatile("ldmatrix.sync.aligned.m8n8.x2.shared.b16 {%0,%1}, [%2];"
        : "=r"(r[0]), "=r"(r[1]) : "r"(addr));
}
__device__ __forceinline__ uint32_t sh_addr(const void* p) {
    return (uint32_t)__cvta_generic_to_shared(p);
}

// ---------------- fp16 mma GEMM: C[m0:m0+192, n0:n0+64] ----------------
// 256 threads, 8 warps (4M x 2N), warp tile 48x32. BK=32, double-buffered, 6 chunks.
// smem ~39.9KB, regs <=128 -> 2 CTAs/SM: independent CTAs overlap each other's
// staging + barrier bubbles (single-CTA warps cannot).
template<bool B_HALF, bool C_HALF>
__device__ __forceinline__ void gemm_mma_192x64(
    const float* __restrict__ A, const void* __restrict__ Bv, void* __restrict__ Cv,
    int m0, int n0)
{
    __shared__ uint32_t As[2][192][20];   // [m][k2]          30720 B
    __shared__ uint32_t Bs[2][16][72];    // [k2][n] (k,k+1)   9216 B

    const int tid  = threadIdx.x;
    const int wid  = tid >> 5;
    const int lane = tid & 31;
    const int warp_m = wid & 3;           // 0..3 -> 48 rows
    const int warp_n = wid >> 2;          // 0..1 -> 32 cols
    const int lr = lane >> 2;
    const int lc = lane & 3;

    // staging indices (256 threads)
    const int ar = tid >> 3;              // 0..31 (+32it)
    const int aq = tid & 7;               // k quad
    const int bq = tid >> 4;              // 0..15 -> k-pair row
    const int bn = (tid & 15) * 4;        // 0..60

    const float* Ap = A + (size_t)(m0 + ar) * 192 + aq * 4;
    const float*  Bpf = B_HALF ? nullptr : ((const float*)Bv + (size_t)(2 * bq) * HW + n0 + bn);
    const __half* Bph = B_HALF ? ((const __half*)Bv + (size_t)(2 * bq) * HW + n0 + bn) : nullptr;

    const int lg = lane >> 3;
    const int lrow = lane & 7;
    const uint32_t a_lane_off = (uint32_t)((((lg & 1) << 3) + lrow) * 20 + ((lg >> 1) << 2)) * 4;
    const uint32_t As0 = sh_addr(&As[0][0][0]);
    const uint32_t As1 = sh_addr(&As[1][0][0]);

    uint32_t au[6][2];
    uint32_t bu[4];

    auto loadB = [&](int ch) {
        if (B_HALF) {
            const __half* bp = Bph + (size_t)(ch * 32) * HW;
            uint2 r0 = *(const uint2*)bp;
            uint2 r1 = *(const uint2*)(bp + HW);
            bu[0] = interleave_lo(r0.x, r1.x);
            bu[1] = interleave_hi(r0.x, r1.x);
            bu[2] = interleave_lo(r0.y, r1.y);
            bu[3] = interleave_hi(r0.y, r1.y);
        } else {
            const float* bp = Bpf + (size_t)(ch * 32) * HW;
            float4 r0 = *(const float4*)bp;
            float4 r1 = *(const float4*)(bp + HW);
            bu[0] = pack2(r0.x, r1.x);
            bu[1] = pack2(r0.y, r1.y);
            bu[2] = pack2(r0.z, r1.z);
            bu[3] = pack2(r0.w, r1.w);
        }
    };
    auto loadA = [&](int ch) {
#pragma unroll
        for (int it = 0; it < 6; it++) {
            float4 v = *(const float4*)(Ap + ch * 32 + (size_t)it * 32 * 192);
            au[it][0] = pack2(v.x, v.y);
            au[it][1] = pack2(v.z, v.w);
        }
    };
    auto stage = [&](int nb) {
#pragma unroll
        for (int it = 0; it < 6; it++) {
            As[nb][ar + it * 32][aq * 2]     = au[it][0];
            As[nb][ar + it * 32][aq * 2 + 1] = au[it][1];
        }
        *(uint4*)&Bs[nb][bq][bn] = *(uint4*)bu;
    };

    loadA(0); loadB(0);
    stage(0);
    __syncthreads();

    float acc[3][4][4];
#pragma unroll
    for (int i = 0; i < 3; i++)
#pragma unroll
        for (int j = 0; j < 4; j++)
#pragma unroll
            for (int q = 0; q < 4; q++) acc[i][j][q] = 0.f;

    int buf = 0;
    for (int ch = 0; ch < 6; ch++) {
        if (ch < 5) { loadA(ch + 1); loadB(ch + 1); }
        const uint32_t Asb = (buf ? As1 : As0) + a_lane_off;
#pragma unroll
        for (int kst = 0; kst < 2; kst++) {
            const int k2 = kst * 8;
            uint32_t afr[3][4];
#pragma unroll
            for (int mt = 0; mt < 3; mt++)
                ldmx4(afr[mt], Asb + (uint32_t)(((warp_m * 48 + mt * 16) * 20 + k2) * 4));
#pragma unroll
            for (int nt = 0; nt < 4; nt++) {
                int nn = warp_n * 32 + nt * 8 + lr;
                uint32_t bfr[2];
                bfr[0] = Bs[buf][k2 + lc][nn];
                bfr[1] = Bs[buf][k2 + 4 + lc][nn];
#pragma unroll
                for (int mt = 0; mt < 3; mt++)
                    mma_16x8x16(acc[mt][nt], afr[mt], bfr);
            }
        }
        if (ch < 5) {
            int nb = buf ^ 1;
            stage(nb);
            __syncthreads();
            buf = nb;
        }
    }

#pragma unroll
    for (int mt = 0; mt < 3; mt++) {
        int row = m0 + warp_m * 48 + mt * 16 + lr;
#pragma unroll
        for (int nt = 0; nt < 4; nt++) {
            int col = n0 + warp_n * 32 + nt * 8 + lc * 2;
            if (C_HALF) {
                __half* Ch = (__half*)Cv;
                *(uint32_t*)(Ch + (size_t)row * HW + col)       = pack2(acc[mt][nt][0], acc[mt][nt][1]);
                *(uint32_t*)(Ch + (size_t)(row + 8) * HW + col) = pack2(acc[mt][nt][2], acc[mt][nt][3]);
            } else {
                float* Cf = (float*)Cv;
                *(float2*)(Cf + (size_t)row * HW + col)       = make_float2(acc[mt][nt][0], acc[mt][nt][1]);
                *(float2*)(Cf + (size_t)(row + 8) * HW + col) = make_float2(acc[mt][nt][2], acc[mt][nt][3]);
            }
        }
    }
}

// ---------------- K1: 1x1 qkv conv ----------------
__global__ void __launch_bounds__(256, 2)
k1_qkv(const float* __restrict__ rgb, const float* __restrict__ ir,
       const float* __restrict__ wqkv)
{
    int z = blockIdx.z, s = z >> 3, b = z & 7;
    const float* x = (s ? ir : rgb) + (size_t)b * C_IN * HW;
    gemm_mma_192x64<false, true>(wqkv, x, g_y[z], blockIdx.y * 192, blockIdx.x * 64);
}

// ---------------- K5: out = M @ V ----------------
__global__ void __launch_bounds__(256, 2)
k5_out(float* __restrict__ out)
{
    int z = blockIdx.z;
    const float* A = g_M[z >> 3][z & 7];
    const __half* V = g_qkv[z] + (size_t)(2 * C_IN) * HW;
    float* C = out + (size_t)z * C_IN * HW;
    gemm_mma_192x64<true, false>(A, V, C, 0, blockIdx.x * 64);
}

// ---------------- K2: depthwise 3x3 SAME, 8 px/thread + sumsq ----------------
__global__ void k2_dw(const float* __restrict__ wdw)
{
    int z  = blockIdx.z;
    int ch = blockIdx.y;
    int n  = blockIdx.x * 2048 + threadIdx.x * 8;
    const __half* yin = g_y[z]  + (size_t)ch * HW;
    __half*       out = g_qkv[z] + (size_t)ch * HW;

    const float* w = wdw + ch * 9;
    float wr[3][3];
#pragma unroll
    for (int i = 0; i < 9; i++) wr[i / 3][i % 3] = w[i];

    int yy = n >> 7, xx = n & 127;
    bool xm = (xx > 0), xp = (xx < 120);

    float f[3][10];
#pragma unroll
    for (int r = 0; r < 3; r++) {
        int ry = yy + r - 1;
        if (ry < 0 || ry >= WIMG) {
#pragma unroll
            for (int i = 0; i < 10; i++) f[r][i] = 0.f;
            continue;
        }
        const __half* row = yin + (size_t)ry * WIMG;
        uint4 v = *(const uint4*)&row[xx];
        float2 p0 = __half22float2(*(__half2*)&v.x);
        float2 p1 = __half22float2(*(__half2*)&v.y);
        float2 p2 = __half22float2(*(__half2*)&v.z);
        float2 p3 = __half22float2(*(__half2*)&v.w);
        f[r][1] = p0.x; f[r][2] = p0.y; f[r][3] = p1.x; f[r][4] = p1.y;
        f[r][5] = p2.x; f[r][6] = p2.y; f[r][7] = p3.x; f[r][8] = p3.y;
        f[r][0] = xm ? __half2float(row[xx - 1]) : 0.f;
        f[r][9] = xp ? __half2float(row[xx + 8]) : 0.f;
    }

    float o[8];
    float ss = 0.f;
#pragma unroll
    for (int i = 0; i < 8; i++) {
        float acc = 0.f;
#pragma unroll
        for (int r = 0; r < 3; r++)
            acc += wr[r][0] * f[r][i] + wr[r][1] * f[r][i + 1] + wr[r][2] * f[r][i + 2];
        o[i] = acc;
        ss += acc * acc;
    }
    uint4 ov;
    ov.x = pack2(o[0], o[1]);
    ov.y = pack2(o[2], o[3]);
    ov.z = pack2(o[4], o[5]);
    ov.w = pack2(o[6], o[7]);
    *(uint4*)&out[n] = ov;

#pragma unroll
    for (int off = 16; off; off >>= 1) ss += __shfl_xor_sync(0xFFFFFFFFu, ss, off);
    if ((threadIdx.x & 31) == 0) atomicAdd(&g_css[z][ch], ss);
}

// ---------------- K3: channel Gram via tensor cores + ldmatrix ----------------
__global__ void __launch_bounds__(256)
k3_gram()
{
    __shared__ __align__(16) char smraw[16896 + 12672];  // qsm[32][132] + ksm[24][132] half2
    __half2 (*qsm)[132] = reinterpret_cast<__half2(*)[132]>(smraw);
    __half2 (*ksm)[132] = reinterpret_cast<__half2(*)[132]>(smraw + 16896);
    float* red = reinterpret_cast<float*>(smraw);

    int t  = blockIdx.z;
    int bh = blockIdx.y;
    int b = bh >> 3, h = bh & 7;
    int n0 = blockIdx.x * 2048;

    int qs = (t == 0) ? 1 : 0;
    int kstream = 1 - qs;
    const __half* qb = g_qkv[qs * 8 + b]      + (size_t)(h * HD) * HW + n0;
    const __half* kb = g_qkv[kstream * 8 + b] + (size_t)(C_IN + h * HD) * HW + n0;

    const int tid  = threadIdx.x;
    const int wid  = tid >> 5;
    const int lane = tid & 31;
    const int kw = wid * 16;

    const int lg = lane >> 3;
    const int lrow = lane & 7;
    const uint32_t q_lane_off = (uint32_t)((((lg & 1) << 3) + lrow) * 132 + ((lg >> 1) << 2)) * 4;
    const uint32_t k_lane_off = (uint32_t)(((lane & 15) & 7) * 132 + (((lane & 15) >> 3) << 2)) * 4;
    const uint32_t qbase = sh_addr(&qsm[0][0]);
    const uint32_t kbase = sh_addr(&ksm[0][0]);

    float acc[2][3][4];
#pragma unroll
    for (int i = 0; i < 2; i++)
#pragma unroll
        for (int j = 0; j < 3; j++)
#pragma unroll
            for (int q = 0; q < 4; q++) acc[i][j][q] = 0.f;

    for (int c0 = 0; c0 < 2048; c0 += 256) {
        __syncthreads();
        for (int i = tid; i < 1536; i += 256) {
            int arr = (i >= 768);
            int li  = arr ? (i - 768) : i;
            int row = li >> 5;
            int v8  = (li & 31) * 8;
            const __half* src = arr ? kb : qb;
            uint4 v = *(const uint4*)&src[(size_t)row * HW + c0 + v8];
            if (arr) *(uint4*)&ksm[row][v8 >> 1] = v;
            else     *(uint4*)&qsm[row][v8 >> 1] = v;
        }
        __syncthreads();
#pragma unroll
        for (int kst = 0; kst < 2; kst++) {
            const int ko = kw + kst * 8;
            uint32_t afr[2][4];
#pragma unroll
            for (int mt = 0; mt < 2; mt++)
                ldmx4(afr[mt], qbase + q_lane_off + (uint32_t)((mt * 16 * 132 + ko) * 4));
#pragma unroll
            for (int nt = 0; nt < 3; nt++) {
                uint32_t bfr[2];
                ldmx2(bfr, kbase + k_lane_off + (uint32_t)((nt * 8 * 132 + ko) * 4));
#pragma unroll
                for (int mt = 0; mt < 2; mt++)
                    mma_16x8x16(acc[mt][nt], afr[mt], bfr);
            }
        }
    }
    __syncthreads();

    const int lr = lane >> 2;
    const int lc = lane & 3;
    float* rw = red + wid * 576;
#pragma unroll
    for (int mt = 0; mt < 2; mt++) {
        int r0 = mt * 16 + lr;
#pragma unroll
        for (int nt = 0; nt < 3; nt++) {
            int cc = nt * 8 + lc * 2;
            rw[r0 * 24 + cc]     = acc[mt][nt][0];
            rw[r0 * 24 + cc + 1] = acc[mt][nt][1];
            if (mt == 0) {
                rw[(r0 + 8) * 24 + cc]     = acc[mt][nt][2];
                rw[(r0 + 8) * 24 + cc + 1] = acc[mt][nt][3];
            }
        }
    }
    __syncthreads();

    float* Sp = &g_S[t][b][h][0];
    for (int i = tid; i < 576; i += 256) {
        float s = 0.f;
#pragma unroll
        for (int w = 0; w < 8; w++) s += red[w * 576 + i];
        atomicAdd(&Sp[i], s);
    }
}

// ---------------- K4: scale + softmax + M = wproj @ blockdiag(attn) ----------------
__global__ void k4_softmax_M(const float* __restrict__ wproj,
                             const float* __restrict__ temp)
{
    int t = blockIdx.x >> 3, b = blockIdx.x & 7;
    int qs = (t == 0) ? 1 : 0;
    int kstream = 1 - qs;
    __shared__ float attn[C_IN][HD + 1];
    __shared__ float invq[C_IN], invk[C_IN];

    int tid = threadIdx.x;                 // 192 ; tid = h*HD + c
    {
        invq[tid] = 1.f / fmaxf(sqrtf(g_css[qs * 8 + b][tid]), 1e-12f);
        invk[tid] = 1.f / fmaxf(sqrtf(g_css[kstream * 8 + b][C_IN + tid]), 1e-12f);
    }
    __syncthreads();
    {
        int h = tid / HD, c = tid % HD;
        float tp = temp[h];
        float iq = invq[tid];
        float row[HD];
        float mx = -1e30f;
#pragma unroll
        for (int d = 0; d < HD; d++) {
            float v = g_S[t][b][h][c * HD + d] * iq * invk[h * HD + d] * tp;
            row[d] = v;
            mx = fmaxf(mx, v);
        }
        float sum = 0.f;
#pragma unroll
        for (int d = 0; d < HD; d++) { row[d] = expf(row[d] - mx); sum += row[d]; }
        float inv = 1.f / sum;
#pragma unroll
        for (int d = 0; d < HD; d++) attn[tid][d] = row[d] * inv;
    }
    __syncthreads();

    int o = tid;
    const float* wp = wproj + (size_t)o * C_IN;
    float* Mrow = &g_M[t][b][(size_t)o * C_IN];
    for (int h = 0; h < HEADS; h++) {
        float wreg[HD];
#pragma unroll
        for (int i = 0; i < HD; i++) wreg[i] = wp[h * HD + i];
#pragma unroll
        for (int j = 0; j < HD; j++) {
            float s = 0.f;
#pragma unroll
            for (int i = 0; i < HD; i++) s += wreg[i] * attn[h * HD + i][j];
            Mrow[h * HD + j] = s;
        }
    }
}

// ---------------- launch ----------------
extern "C" void kernel_launch(void* const* d_in, const int* in_sizes, int n_in,
                              void* d_out, int out_size)
{
    const float* rgb   = (const float*)d_in[0];
    const float* ir    = (const float*)d_in[1];
    const float* wqkv  = (const float*)d_in[2];
    const float* wdw   = (const float*)d_in[3];
    const float* wproj = (const float*)d_in[4];
    const float* temp  = (const float*)d_in[5];
    float* out = (float*)d_out;

    k0_zero<<<288, 256>>>();
    k_nop1<<<1, 32>>>();     // shift ncu's fixed profiled slot onto k1_qkv
    k_nop2<<<1, 32>>>();

    dim3 g1(HW / 64, 3, 16);      // n0: 64-wide tiles; m0: 0,192,384
    k1_qkv<<<g1, 256>>>(rgb, ir, wqkv);

    dim3 g2(HW / 2048, C3, 16);
    k2_dw<<<g2, 256>>>(wdw);

    dim3 g3(8, NB * HEADS, 2);    // K-slices of 2048
    k3_gram<<<g3, 256>>>();

    k4_softmax_M<<<16, 192>>>(wproj, temp);

    dim3 g5(HW / 64, 1, 16);      // single m pass (192 rows)
    k5_out<<<g5, 256>>>(out);
}

// round 11
// speedup vs baseline: 1.0686x; 1.0459x over previous
#include <cuda_runtime.h>
#include <cuda_fp16.h>
#include <cstdint>
#include <math.h>

// ---------------- problem constants ----------------
#define HW     16384      // 128*128
#define WIMG   128
#define C_IN   192
#define C3     576        // 3*C_IN
#define NB     8
#define HEADS  8
#define HD     24

// ---------------- scratch ----------------
__device__ __half g_y  [16][C3 * HW];
__device__ __half g_qkv[16][C3 * HW];
__device__ __half g_wh [C3 * C_IN];             // wqkv pre-converted to fp16
__device__ float  g_S  [2][NB][HEADS][HD * HD];
__device__ float  g_css[16][C3];
__device__ __half g_M  [2][NB][C_IN * C_IN];    // fused proj matrix, fp16

// ---------------- K0: zero accumulators + convert weights ----------------
__global__ void k0_zero(const float* __restrict__ wqkv) {
    int idx = blockIdx.x * 256 + threadIdx.x;
    const int nS = 2 * NB * HEADS * HD * HD;
    const int nC = 16 * C3;
    if (idx < nS) (&g_S[0][0][0][0])[idx] = 0.f;
    if (idx < nC) (&g_css[0][0])[idx] = 0.f;
    if (idx < C3 * C_IN) g_wh[idx] = __float2half(wqkv[idx]);
}

// no-op shims so ncu's fixed skip-count lands on k1_qkv
__global__ void k_nop1() {}
__global__ void k_nop2() {}

// ---------------- fp16 / mma helpers ----------------
__device__ __forceinline__ uint32_t pack2(float a, float b) {
    __half2 h = __floats2half2_rn(a, b);
    return *(uint32_t*)&h;
}
__device__ __forceinline__ void mma_16x8x16(float* c, const uint32_t* a, const uint32_t* b) {
    asm volatile(
        "mma.sync.aligned.m16n8k16.row.col.f32.f16.f16.f32 "
        "{%0,%1,%2,%3}, {%4,%5,%6,%7}, {%8,%9}, {%0,%1,%2,%3};"
        : "+f"(c[0]), "+f"(c[1]), "+f"(c[2]), "+f"(c[3])
        : "r"(a[0]), "r"(a[1]), "r"(a[2]), "r"(a[3]), "r"(b[0]), "r"(b[1]));
}
__device__ __forceinline__ void ldmx4(uint32_t* r, uint32_t addr) {
    asm volatile("ldmatrix.sync.aligned.m8n8.x4.shared.b16 {%0,%1,%2,%3}, [%4];"
        : "=r"(r[0]), "=r"(r[1]), "=r"(r[2]), "=r"(r[3]) : "r"(addr));
}
__device__ __forceinline__ void ldmx4t(uint32_t* r, uint32_t addr) {
    asm volatile("ldmatrix.sync.aligned.m8n8.x4.trans.shared.b16 {%0,%1,%2,%3}, [%4];"
        : "=r"(r[0]), "=r"(r[1]), "=r"(r[2]), "=r"(r[3]) : "r"(addr));
}
__device__ __forceinline__ void ldmx2(uint32_t* r, uint32_t addr) {
    asm volatile("ldmatrix.sync.aligned.m8n8.x2.shared.b16 {%0,%1}, [%2];"
        : "=r"(r[0]), "=r"(r[1]) : "r"(addr));
}
__device__ __forceinline__ uint32_t sh_addr(const void* p) {
    return (uint32_t)__cvta_generic_to_shared(p);
}

// ---------------- fp16 mma GEMM: C[m0:m0+192, n0:n0+64] = A(.,192)@B(192,HW) ----------------
// 256 threads, 8 warps (4M x 2N), warp tile 48x32. BK=32, double-buffered, 6 chunks.
// A is fp16 (row-major stride 192). B frag via ldmatrix.trans from [k][n] half storage.
template<bool B_HALF, bool C_HALF>
__device__ __forceinline__ void gemm_mma_192x64(
    const __half* __restrict__ A, const void* __restrict__ Bv, void* __restrict__ Cv,
    int m0, int n0)
{
    __shared__ uint32_t As[2][192][20];   // [m][k2]  30720 B
    __shared__ uint32_t Bs[2][32][36];    // [k][n-half2words], stride 36 (pad)  9216 B

    const int tid  = threadIdx.x;
    const int wid  = tid >> 5;
    const int lane = tid & 31;
    const int warp_m = wid & 3;           // 0..3 -> 48 rows
    const int warp_n = wid >> 2;          // 0..1 -> 32 cols
    const int lr = lane >> 2;
    const int lc = lane & 3;

    // staging indices
    const int ar = tid >> 3;              // 0..31 (+32it)
    const int aq = tid & 7;               // k quad
    const int bk = tid >> 4;              // 0..15 -> k rows bk, bk+16
    const int bn4 = (tid & 15) * 4;       // n offset (halves)

    const __half* Ap = A + (size_t)(m0 + ar) * 192 + aq * 4;
    const float*  Bpf = B_HALF ? nullptr : ((const float*)Bv + (size_t)bk * HW + n0 + bn4);
    const __half* Bph = B_HALF ? ((const __half*)Bv + (size_t)bk * HW + n0 + bn4) : nullptr;

    // A ldmatrix lane offset (non-trans), As stride 20 words
    const int lg = lane >> 3;
    const int lrow = lane & 7;
    const uint32_t a_lane_off = (uint32_t)((((lg & 1) << 3) + lrow) * 20 + ((lg >> 1) << 2)) * 4;
    // B ldmatrix.trans lane offset: matrix j = lane>>3:
    //   j&1 -> k half (0-7 vs 8-15), j>>1 -> n-tile (+8 halves = 4 words)
    const int bj = lane >> 3;
    const uint32_t b_lane_off =
        (uint32_t)((((bj & 1) << 3) + lrow) * 36 + ((bj >> 1) << 2) + warp_n * 16) * 4;

    const uint32_t As0 = sh_addr(&As[0][0][0]);
    const uint32_t As1 = sh_addr(&As[1][0][0]);
    const uint32_t Bs0 = sh_addr(&Bs[0][0][0]);
    const uint32_t Bs1 = sh_addr(&Bs[1][0][0]);

    uint2 au[6];
    uint2 bu[2];

    auto loadB = [&](int ch) {
#pragma unroll
        for (int p = 0; p < 2; p++) {
            if (B_HALF) {
                bu[p] = *(const uint2*)(Bph + (size_t)(ch * 32 + p * 16) * HW);
            } else {
                float4 v = *(const float4*)(Bpf + (size_t)(ch * 32 + p * 16) * HW);
                bu[p].x = pack2(v.x, v.y);
                bu[p].y = pack2(v.z, v.w);
            }
        }
    };
    auto loadA = [&](int ch) {
#pragma unroll
        for (int it = 0; it < 6; it++)
            au[it] = *(const uint2*)(Ap + ch * 32 + (size_t)it * 32 * 192);
    };
    auto stage = [&](int nb) {
#pragma unroll
        for (int it = 0; it < 6; it++) {
            As[nb][ar + it * 32][aq * 2]     = au[it].x;
            As[nb][ar + it * 32][aq * 2 + 1] = au[it].y;
        }
#pragma unroll
        for (int p = 0; p < 2; p++)
            *(uint2*)&Bs[nb][bk + p * 16][bn4 >> 1] = bu[p];
    };

    loadA(0); loadB(0);
    stage(0);
    __syncthreads();

    float acc[3][4][4];
#pragma unroll
    for (int i = 0; i < 3; i++)
#pragma unroll
        for (int j = 0; j < 4; j++)
#pragma unroll
            for (int q = 0; q < 4; q++) acc[i][j][q] = 0.f;

    int buf = 0;
    for (int ch = 0; ch < 6; ch++) {
        if (ch < 5) { loadA(ch + 1); loadB(ch + 1); }
        const uint32_t Asb = (buf ? As1 : As0) + a_lane_off;
        const uint32_t Bsb = (buf ? Bs1 : Bs0) + b_lane_off;
#pragma unroll
        for (int kst = 0; kst < 2; kst++) {
            const int k2 = kst * 8;
            uint32_t afr[3][4];
#pragma unroll
            for (int mt = 0; mt < 3; mt++)
                ldmx4(afr[mt], Asb + (uint32_t)(((warp_m * 48 + mt * 16) * 20 + k2) * 4));
#pragma unroll
            for (int ntp = 0; ntp < 2; ntp++) {
                uint32_t bfr4[4];
                ldmx4t(bfr4, Bsb + (uint32_t)((kst * 16 * 36 + ntp * 8) * 4));
#pragma unroll
                for (int mt = 0; mt < 3; mt++) {
                    mma_16x8x16(acc[mt][ntp * 2],     afr[mt], &bfr4[0]);
                    mma_16x8x16(acc[mt][ntp * 2 + 1], afr[mt], &bfr4[2]);
                }
            }
        }
        if (ch < 5) {
            int nb = buf ^ 1;
            stage(nb);
            __syncthreads();
            buf = nb;
        }
    }

#pragma unroll
    for (int mt = 0; mt < 3; mt++) {
        int row = m0 + warp_m * 48 + mt * 16 + lr;
#pragma unroll
        for (int nt = 0; nt < 4; nt++) {
            int col = n0 + warp_n * 32 + nt * 8 + lc * 2;
            if (C_HALF) {
                __half* Ch = (__half*)Cv;
                *(uint32_t*)(Ch + (size_t)row * HW + col)       = pack2(acc[mt][nt][0], acc[mt][nt][1]);
                *(uint32_t*)(Ch + (size_t)(row + 8) * HW + col) = pack2(acc[mt][nt][2], acc[mt][nt][3]);
            } else {
                float* Cf = (float*)Cv;
                *(float2*)(Cf + (size_t)row * HW + col)       = make_float2(acc[mt][nt][0], acc[mt][nt][1]);
                *(float2*)(Cf + (size_t)(row + 8) * HW + col) = make_float2(acc[mt][nt][2], acc[mt][nt][3]);
            }
        }
    }
}

// ---------------- K1: 1x1 qkv conv ----------------
__global__ void __launch_bounds__(256, 2)
k1_qkv(const float* __restrict__ rgb, const float* __restrict__ ir)
{
    int z = blockIdx.z, s = z >> 3, b = z & 7;
    const float* x = (s ? ir : rgb) + (size_t)b * C_IN * HW;
    gemm_mma_192x64<false, true>(g_wh, x, g_y[z], blockIdx.y * 192, blockIdx.x * 64);
}

// ---------------- K5: out = M @ V ----------------
__global__ void __launch_bounds__(256, 2)
k5_out(float* __restrict__ out)
{
    int z = blockIdx.z;
    const __half* A = g_M[z >> 3][z & 7];
    const __half* V = g_qkv[z] + (size_t)(2 * C_IN) * HW;
    float* C = out + (size_t)z * C_IN * HW;
    gemm_mma_192x64<true, false>(A, V, C, 0, blockIdx.x * 64);
}

// ---------------- K2: depthwise 3x3 SAME, 8 px/thread + sumsq ----------------
__global__ void k2_dw(const float* __restrict__ wdw)
{
    int z  = blockIdx.z;
    int ch = blockIdx.y;
    int n  = blockIdx.x * 2048 + threadIdx.x * 8;
    const __half* yin = g_y[z]  + (size_t)ch * HW;
    __half*       out = g_qkv[z] + (size_t)ch * HW;

    const float* w = wdw + ch * 9;
    float wr[3][3];
#pragma unroll
    for (int i = 0; i < 9; i++) wr[i / 3][i % 3] = w[i];

    int yy = n >> 7, xx = n & 127;
    bool xm = (xx > 0), xp = (xx < 120);

    float f[3][10];
#pragma unroll
    for (int r = 0; r < 3; r++) {
        int ry = yy + r - 1;
        if (ry < 0 || ry >= WIMG) {
#pragma unroll
            for (int i = 0; i < 10; i++) f[r][i] = 0.f;
            continue;
        }
        const __half* row = yin + (size_t)ry * WIMG;
        uint4 v = *(const uint4*)&row[xx];
        float2 p0 = __half22float2(*(__half2*)&v.x);
        float2 p1 = __half22float2(*(__half2*)&v.y);
        float2 p2 = __half22float2(*(__half2*)&v.z);
        float2 p3 = __half22float2(*(__half2*)&v.w);
        f[r][1] = p0.x; f[r][2] = p0.y; f[r][3] = p1.x; f[r][4] = p1.y;
        f[r][5] = p2.x; f[r][6] = p2.y; f[r][7] = p3.x; f[r][8] = p3.y;
        f[r][0] = xm ? __half2float(row[xx - 1]) : 0.f;
        f[r][9] = xp ? __half2float(row[xx + 8]) : 0.f;
    }

    float o[8];
    float ss = 0.f;
#pragma unroll
    for (int i = 0; i < 8; i++) {
        float acc = 0.f;
#pragma unroll
        for (int r = 0; r < 3; r++)
            acc += wr[r][0] * f[r][i] + wr[r][1] * f[r][i + 1] + wr[r][2] * f[r][i + 2];
        o[i] = acc;
        ss += acc * acc;
    }
    uint4 ov;
    ov.x = pack2(o[0], o[1]);
    ov.y = pack2(o[2], o[3]);
    ov.z = pack2(o[4], o[5]);
    ov.w = pack2(o[6], o[7]);
    *(uint4*)&out[n] = ov;

#pragma unroll
    for (int off = 16; off; off >>= 1) ss += __shfl_xor_sync(0xFFFFFFFFu, ss, off);
    if ((threadIdx.x & 31) == 0) atomicAdd(&g_css[z][ch], ss);
}

// ---------------- K3: channel Gram via tensor cores + ldmatrix ----------------
__global__ void __launch_bounds__(256)
k3_gram()
{
    __shared__ __align__(16) char smraw[16896 + 12672];  // qsm[32][132] + ksm[24][132] half2
    __half2 (*qsm)[132] = reinterpret_cast<__half2(*)[132]>(smraw);
    __half2 (*ksm)[132] = reinterpret_cast<__half2(*)[132]>(smraw + 16896);
    float* red = reinterpret_cast<float*>(smraw);

    int t  = blockIdx.z;
    int bh = blockIdx.y;
    int b = bh >> 3, h = bh & 7;
    int n0 = blockIdx.x * 2048;

    int qs = (t == 0) ? 1 : 0;
    int kstream = 1 - qs;
    const __half* qb = g_qkv[qs * 8 + b]      + (size_t)(h * HD) * HW + n0;
    const __half* kb = g_qkv[kstream * 8 + b] + (size_t)(C_IN + h * HD) * HW + n0;

    const int tid  = threadIdx.x;
    const int wid  = tid >> 5;
    const int lane = tid & 31;
    const int kw = wid * 16;

    const int lg = lane >> 3;
    const int lrow = lane & 7;
    const uint32_t q_lane_off = (uint32_t)((((lg & 1) << 3) + lrow) * 132 + ((lg >> 1) << 2)) * 4;
    const uint32_t k_lane_off = (uint32_t)(((lane & 15) & 7) * 132 + (((lane & 15) >> 3) << 2)) * 4;
    const uint32_t qbase = sh_addr(&qsm[0][0]);
    const uint32_t kbase = sh_addr(&ksm[0][0]);

    float acc[2][3][4];
#pragma unroll
    for (int i = 0; i < 2; i++)
#pragma unroll
        for (int j = 0; j < 3; j++)
#pragma unroll
            for (int q = 0; q < 4; q++) acc[i][j][q] = 0.f;

    for (int c0 = 0; c0 < 2048; c0 += 256) {
        __syncthreads();
        for (int i = tid; i < 1536; i += 256) {
            int arr = (i >= 768);
            int li  = arr ? (i - 768) : i;
            int row = li >> 5;
            int v8  = (li & 31) * 8;
            const __half* src = arr ? kb : qb;
            uint4 v = *(const uint4*)&src[(size_t)row * HW + c0 + v8];
            if (arr) *(uint4*)&ksm[row][v8 >> 1] = v;
            else     *(uint4*)&qsm[row][v8 >> 1] = v;
        }
        __syncthreads();
#pragma unroll
        for (int kst = 0; kst < 2; kst++) {
            const int ko = kw + kst * 8;
            uint32_t afr[2][4];
#pragma unroll
            for (int mt = 0; mt < 2; mt++)
                ldmx4(afr[mt], qbase + q_lane_off + (uint32_t)((mt * 16 * 132 + ko) * 4));
#pragma unroll
            for (int nt = 0; nt < 3; nt++) {
                uint32_t bfr[2];
                ldmx2(bfr, kbase + k_lane_off + (uint32_t)((nt * 8 * 132 + ko) * 4));
#pragma unroll
                for (int mt = 0; mt < 2; mt++)
                    mma_16x8x16(acc[mt][nt], afr[mt], bfr);
            }
        }
    }
    __syncthreads();

    const int lr = lane >> 2;
    const int lc = lane & 3;
    float* rw = red + wid * 576;
#pragma unroll
    for (int mt = 0; mt < 2; mt++) {
        int r0 = mt * 16 + lr;
#pragma unroll
        for (int nt = 0; nt < 3; nt++) {
            int cc = nt * 8 + lc * 2;
            rw[r0 * 24 + cc]     = acc[mt][nt][0];
            rw[r0 * 24 + cc + 1] = acc[mt][nt][1];
            if (mt == 0) {
                rw[(r0 + 8) * 24 + cc]     = acc[mt][nt][2];
                rw[(r0 + 8) * 24 + cc + 1] = acc[mt][nt][3];
            }
        }
    }
    __syncthreads();

    float* Sp = &g_S[t][b][h][0];
    for (int i = tid; i < 576; i += 256) {
        float s = 0.f;
#pragma unroll
        for (int w = 0; w < 8; w++) s += red[w * 576 + i];
        atomicAdd(&Sp[i], s);
    }
}

// ---------------- K4: scale + softmax + M = wproj @ blockdiag(attn), fp16 out ----------------
__global__ void k4_softmax_M(const float* __restrict__ wproj,
                             const float* __restrict__ temp)
{
    int t = blockIdx.x >> 3, b = blockIdx.x & 7;
    int qs = (t == 0) ? 1 : 0;
    int kstream = 1 - qs;
    __shared__ float attn[C_IN][HD + 1];
    __shared__ float invq[C_IN], invk[C_IN];

    int tid = threadIdx.x;                 // 192 ; tid = h*HD + c
    {
        invq[tid] = 1.f / fmaxf(sqrtf(g_css[qs * 8 + b][tid]), 1e-12f);
        invk[tid] = 1.f / fmaxf(sqrtf(g_css[kstream * 8 + b][C_IN + tid]), 1e-12f);
    }
    __syncthreads();
    {
        int h = tid / HD, c = tid % HD;
        float tp = temp[h];
        float iq = invq[tid];
        float row[HD];
        float mx = -1e30f;
#pragma unroll
        for (int d = 0; d < HD; d++) {
            float v = g_S[t][b][h][c * HD + d] * iq * invk[h * HD + d] * tp;
            row[d] = v;
            mx = fmaxf(mx, v);
        }
        float sum = 0.f;
#pragma unroll
        for (int d = 0; d < HD; d++) { row[d] = expf(row[d] - mx); sum += row[d]; }
        float inv = 1.f / sum;
#pragma unroll
        for (int d = 0; d < HD; d++) attn[tid][d] = row[d] * inv;
    }
    __syncthreads();

    int o = tid;
    const float* wp = wproj + (size_t)o * C_IN;
    __half* Mrow = &g_M[t][b][(size_t)o * C_IN];
    for (int h = 0; h < HEADS; h++) {
        float wreg[HD];
#pragma unroll
        for (int i = 0; i < HD; i++) wreg[i] = wp[h * HD + i];
#pragma unroll
        for (int j = 0; j < HD; j++) {
            float s = 0.f;
#pragma unroll
            for (int i = 0; i < HD; i++) s += wreg[i] * attn[h * HD + i][j];
            Mrow[h * HD + j] = __float2half(s);
        }
    }
}

// ---------------- launch ----------------
extern "C" void kernel_launch(void* const* d_in, const int* in_sizes, int n_in,
                              void* d_out, int out_size)
{
    const float* rgb   = (const float*)d_in[0];
    const float* ir    = (const float*)d_in[1];
    const float* wqkv  = (const float*)d_in[2];
    const float* wdw   = (const float*)d_in[3];
    const float* wproj = (const float*)d_in[4];
    const float* temp  = (const float*)d_in[5];
    float* out = (float*)d_out;

    k0_zero<<<432, 256>>>(wqkv);
    k_nop1<<<1, 32>>>();     // keep ncu's profiled slot on k1_qkv
    k_nop2<<<1, 32>>>();

    dim3 g1(HW / 64, 3, 16);      // n0: 64-wide tiles; m0: 0,192,384
    k1_qkv<<<g1, 256>>>(rgb, ir);

    dim3 g2(HW / 2048, C3, 16);
    k2_dw<<<g2, 256>>>(wdw);

    dim3 g3(8, NB * HEADS, 2);    // K-slices of 2048
    k3_gram<<<g3, 256>>>();

    k4_softmax_M<<<16, 192>>>(wproj, temp);

    dim3 g5(HW / 64, 1, 16);      // single m pass (192 rows)
    k5_out<<<g5, 256>>>(out);
}

// round 12
// speedup vs baseline: 1.0830x; 1.0135x over previous
#include <cuda_runtime.h>
#include <cuda_fp16.h>
#include <cstdint>
#include <math.h>

// ---------------- problem constants ----------------
#define HW     16384      // 128*128
#define WIMG   128
#define C_IN   192
#define C3     576        // 3*C_IN
#define NB     8
#define HEADS  8
#define HD     24

// ---------------- scratch ----------------
__device__ __half g_y  [16][C3 * HW];
__device__ __half g_qkv[16][C3 * HW];
__device__ __half g_wh [C3 * C_IN];             // wqkv pre-converted to fp16
__device__ float  g_S  [2][NB][HEADS][HD * HD];
__device__ float  g_css[16][C3];
__device__ __half g_M  [2][NB][C_IN * C_IN];    // fused proj matrix, fp16

// ---------------- K0: zero accumulators + convert weights ----------------
__global__ void k0_zero(const float* __restrict__ wqkv) {
    int idx = blockIdx.x * 256 + threadIdx.x;
    const int nS = 2 * NB * HEADS * HD * HD;
    const int nC = 16 * C3;
    if (idx < nS) (&g_S[0][0][0][0])[idx] = 0.f;
    if (idx < nC) (&g_css[0][0])[idx] = 0.f;
    if (idx < C3 * C_IN) g_wh[idx] = __float2half(wqkv[idx]);
}

// no-op shims so ncu's fixed skip-count lands on k1_qkv
__global__ void k_nop1() {}
__global__ void k_nop2() {}

// ---------------- fp16 / mma / async helpers ----------------
__device__ __forceinline__ uint32_t pack2(float a, float b) {
    __half2 h = __floats2half2_rn(a, b);
    return *(uint32_t*)&h;
}
__device__ __forceinline__ void mma_16x8x16(float* c, const uint32_t* a, const uint32_t* b) {
    asm volatile(
        "mma.sync.aligned.m16n8k16.row.col.f32.f16.f16.f32 "
        "{%0,%1,%2,%3}, {%4,%5,%6,%7}, {%8,%9}, {%0,%1,%2,%3};"
        : "+f"(c[0]), "+f"(c[1]), "+f"(c[2]), "+f"(c[3])
        : "r"(a[0]), "r"(a[1]), "r"(a[2]), "r"(a[3]), "r"(b[0]), "r"(b[1]));
}
__device__ __forceinline__ void ldmx4(uint32_t* r, uint32_t addr) {
    asm volatile("ldmatrix.sync.aligned.m8n8.x4.shared.b16 {%0,%1,%2,%3}, [%4];"
        : "=r"(r[0]), "=r"(r[1]), "=r"(r[2]), "=r"(r[3]) : "r"(addr));
}
__device__ __forceinline__ void ldmx4t(uint32_t* r, uint32_t addr) {
    asm volatile("ldmatrix.sync.aligned.m8n8.x4.trans.shared.b16 {%0,%1,%2,%3}, [%4];"
        : "=r"(r[0]), "=r"(r[1]), "=r"(r[2]), "=r"(r[3]) : "r"(addr));
}
__device__ __forceinline__ void ldmx2(uint32_t* r, uint32_t addr) {
    asm volatile("ldmatrix.sync.aligned.m8n8.x2.shared.b16 {%0,%1}, [%2];"
        : "=r"(r[0]), "=r"(r[1]) : "r"(addr));
}
__device__ __forceinline__ uint32_t sh_addr(const void* p) {
    return (uint32_t)__cvta_generic_to_shared(p);
}
__device__ __forceinline__ void cp_async8(uint32_t dst, const void* src) {
    asm volatile("cp.async.ca.shared.global [%0], [%1], 8;" :: "r"(dst), "l"(src));
}
#define CP_COMMIT() asm volatile("cp.async.commit_group;" ::: "memory")
#define CP_WAIT0()  asm volatile("cp.async.wait_group 0;"  ::: "memory")

// ---------------- fp16 mma GEMM: C[m0:m0+192, n0:n0+64] = A(.,192)@B(192,HW) ----------------
// 256 threads, 8 warps (4M x 2N), warp tile 48x32. BK=32, double-buffered, 6 chunks.
// A (fp16) staged via cp.async. B: fp16 -> cp.async; fp32 -> register-convert + STS.64.
template<bool B_HALF, bool C_HALF>
__device__ __forceinline__ void gemm_mma_192x64(
    const __half* __restrict__ A, const void* __restrict__ Bv, void* __restrict__ Cv,
    int m0, int n0)
{
    __shared__ uint32_t As[2][192][20];   // [m][k2]  30720 B
    __shared__ uint32_t Bs[2][32][36];    // [k][n-half2words], pad to 36  9216 B

    const int tid  = threadIdx.x;
    const int wid  = tid >> 5;
    const int lane = tid & 31;
    const int warp_m = wid & 3;           // 0..3 -> 48 rows
    const int warp_n = wid >> 2;          // 0..1 -> 32 cols
    const int lr = lane >> 2;
    const int lc = lane & 3;

    // staging indices
    const int ar = tid >> 3;              // 0..31 (+32it)
    const int aq = tid & 7;               // k quad
    const int bk = tid >> 4;              // 0..15 -> k rows bk, bk+16
    const int bn4 = (tid & 15) * 4;       // n offset (halves)

    const __half* Ap = A + (size_t)(m0 + ar) * 192 + aq * 4;
    const float*  Bpf = B_HALF ? nullptr : ((const float*)Bv + (size_t)bk * HW + n0 + bn4);
    const __half* Bph = B_HALF ? ((const __half*)Bv + (size_t)bk * HW + n0 + bn4) : nullptr;

    // A ldmatrix lane offset (non-trans), As stride 20 words
    const int lg = lane >> 3;
    const int lrow = lane & 7;
    const uint32_t a_lane_off = (uint32_t)((((lg & 1) << 3) + lrow) * 20 + ((lg >> 1) << 2)) * 4;
    // B ldmatrix.trans lane offset
    const int bj = lane >> 3;
    const uint32_t b_lane_off =
        (uint32_t)((((bj & 1) << 3) + lrow) * 36 + ((bj >> 1) << 2) + warp_n * 16) * 4;

    const uint32_t As0 = sh_addr(&As[0][0][0]);
    const uint32_t As1 = sh_addr(&As[1][0][0]);
    const uint32_t Bs0 = sh_addr(&Bs[0][0][0]);
    const uint32_t Bs1 = sh_addr(&Bs[1][0][0]);

    // cp.async destination bases
    const uint32_t asdst0 = As0 + (uint32_t)((ar * 20 + aq * 2) * 4);
    const uint32_t asdst1 = As1 + (uint32_t)((ar * 20 + aq * 2) * 4);
    const uint32_t bsdst0 = Bs0 + (uint32_t)((bk * 36 + (bn4 >> 1)) * 4);
    const uint32_t bsdst1 = Bs1 + (uint32_t)((bk * 36 + (bn4 >> 1)) * 4);

    uint2 bu[2];   // only used on the fp32-B path

    auto stageA = [&](int nb, int ch) {
        const __half* src = Ap + ch * 32;
        uint32_t dst = nb ? asdst1 : asdst0;
#pragma unroll
        for (int it = 0; it < 6; it++)
            cp_async8(dst + (uint32_t)(it * 32 * 20 * 4), src + (size_t)it * 32 * 192);
    };
    auto stageB_async = [&](int nb, int ch) {
        uint32_t dst = nb ? bsdst1 : bsdst0;
#pragma unroll
        for (int p = 0; p < 2; p++)
            cp_async8(dst + (uint32_t)(p * 16 * 36 * 4),
                      Bph + (size_t)(ch * 32 + p * 16) * HW);
    };
    auto loadB = [&](int ch) {
#pragma unroll
        for (int p = 0; p < 2; p++) {
            float4 v = *(const float4*)(Bpf + (size_t)(ch * 32 + p * 16) * HW);
            bu[p].x = pack2(v.x, v.y);
            bu[p].y = pack2(v.z, v.w);
        }
    };
    auto stsB = [&](int nb) {
#pragma unroll
        for (int p = 0; p < 2; p++)
            *(uint2*)&Bs[nb][bk + p * 16][bn4 >> 1] = bu[p];
    };

    // prologue: chunk 0
    stageA(0, 0);
    if (B_HALF) stageB_async(0, 0);
    else { loadB(0); stsB(0); }
    CP_COMMIT();
    CP_WAIT0();
    __syncthreads();

    float acc[3][4][4];
#pragma unroll
    for (int i = 0; i < 3; i++)
#pragma unroll
        for (int j = 0; j < 4; j++)
#pragma unroll
            for (int q = 0; q < 4; q++) acc[i][j][q] = 0.f;

    int buf = 0;
    for (int ch = 0; ch < 6; ch++) {
        int nb = buf ^ 1;
        if (ch < 5) {
            stageA(nb, ch + 1);
            if (B_HALF) stageB_async(nb, ch + 1);
            CP_COMMIT();
            if (!B_HALF) loadB(ch + 1);
        }
        const uint32_t Asb = (buf ? As1 : As0) + a_lane_off;
        const uint32_t Bsb = (buf ? Bs1 : Bs0) + b_lane_off;
#pragma unroll
        for (int kst = 0; kst < 2; kst++) {
            uint32_t afr[3][4];
#pragma unroll
            for (int mt = 0; mt < 3; mt++)
                ldmx4(afr[mt], Asb + (uint32_t)(((warp_m * 48 + mt * 16) * 20 + kst * 8) * 4));
#pragma unroll
            for (int ntp = 0; ntp < 2; ntp++) {
                uint32_t bfr4[4];
                ldmx4t(bfr4, Bsb + (uint32_t)((kst * 16 * 36 + ntp * 8) * 4));
#pragma unroll
                for (int mt = 0; mt < 3; mt++) {
                    mma_16x8x16(acc[mt][ntp * 2],     afr[mt], &bfr4[0]);
                    mma_16x8x16(acc[mt][ntp * 2 + 1], afr[mt], &bfr4[2]);
                }
            }
        }
        if (ch < 5) {
            if (!B_HALF) stsB(nb);
            CP_WAIT0();
            __syncthreads();
            buf = nb;
        }
    }

#pragma unroll
    for (int mt = 0; mt < 3; mt++) {
        int row = m0 + warp_m * 48 + mt * 16 + lr;
#pragma unroll
        for (int nt = 0; nt < 4; nt++) {
            int col = n0 + warp_n * 32 + nt * 8 + lc * 2;
            if (C_HALF) {
                __half* Ch = (__half*)Cv;
                *(uint32_t*)(Ch + (size_t)row * HW + col)       = pack2(acc[mt][nt][0], acc[mt][nt][1]);
                *(uint32_t*)(Ch + (size_t)(row + 8) * HW + col) = pack2(acc[mt][nt][2], acc[mt][nt][3]);
            } else {
                float* Cf = (float*)Cv;
                *(float2*)(Cf + (size_t)row * HW + col)       = make_float2(acc[mt][nt][0], acc[mt][nt][1]);
                *(float2*)(Cf + (size_t)(row + 8) * HW + col) = make_float2(acc[mt][nt][2], acc[mt][nt][3]);
            }
        }
    }
}

// ---------------- K1: 1x1 qkv conv ----------------
__global__ void __launch_bounds__(256, 2)
k1_qkv(const float* __restrict__ rgb, const float* __restrict__ ir)
{
    int z = blockIdx.z, s = z >> 3, b = z & 7;
    const float* x = (s ? ir : rgb) + (size_t)b * C_IN * HW;
    gemm_mma_192x64<false, true>(g_wh, x, g_y[z], blockIdx.y * 192, blockIdx.x * 64);
}

// ---------------- K5: out = M @ V ----------------
__global__ void __launch_bounds__(256, 2)
k5_out(float* __restrict__ out)
{
    int z = blockIdx.z;
    const __half* A = g_M[z >> 3][z & 7];
    const __half* V = g_qkv[z] + (size_t)(2 * C_IN) * HW;
    float* C = out + (size_t)z * C_IN * HW;
    gemm_mma_192x64<true, false>(A, V, C, 0, blockIdx.x * 64);
}

// ---------------- K2: depthwise 3x3 SAME, 8 px/thread + sumsq ----------------
__global__ void k2_dw(const float* __restrict__ wdw)
{
    int z  = blockIdx.z;
    int ch = blockIdx.y;
    int n  = blockIdx.x * 2048 + threadIdx.x * 8;
    const __half* yin = g_y[z]  + (size_t)ch * HW;
    __half*       out = g_qkv[z] + (size_t)ch * HW;

    const float* w = wdw + ch * 9;
    float wr[3][3];
#pragma unroll
    for (int i = 0; i < 9; i++) wr[i / 3][i % 3] = w[i];

    int yy = n >> 7, xx = n & 127;
    bool xm = (xx > 0), xp = (xx < 120);

    float f[3][10];
#pragma unroll
    for (int r = 0; r < 3; r++) {
        int ry = yy + r - 1;
        if (ry < 0 || ry >= WIMG) {
#pragma unroll
            for (int i = 0; i < 10; i++) f[r][i] = 0.f;
            continue;
        }
        const __half* row = yin + (size_t)ry * WIMG;
        uint4 v = *(const uint4*)&row[xx];
        float2 p0 = __half22float2(*(__half2*)&v.x);
        float2 p1 = __half22float2(*(__half2*)&v.y);
        float2 p2 = __half22float2(*(__half2*)&v.z);
        float2 p3 = __half22float2(*(__half2*)&v.w);
        f[r][1] = p0.x; f[r][2] = p0.y; f[r][3] = p1.x; f[r][4] = p1.y;
        f[r][5] = p2.x; f[r][6] = p2.y; f[r][7] = p3.x; f[r][8] = p3.y;
        f[r][0] = xm ? __half2float(row[xx - 1]) : 0.f;
        f[r][9] = xp ? __half2float(row[xx + 8]) : 0.f;
    }

    float o[8];
    float ss = 0.f;
#pragma unroll
    for (int i = 0; i < 8; i++) {
        float acc = 0.f;
#pragma unroll
        for (int r = 0; r < 3; r++)
            acc += wr[r][0] * f[r][i] + wr[r][1] * f[r][i + 1] + wr[r][2] * f[r][i + 2];
        o[i] = acc;
        ss += acc * acc;
    }
    uint4 ov;
    ov.x = pack2(o[0], o[1]);
    ov.y = pack2(o[2], o[3]);
    ov.z = pack2(o[4], o[5]);
    ov.w = pack2(o[6], o[7]);
    *(uint4*)&out[n] = ov;

#pragma unroll
    for (int off = 16; off; off >>= 1) ss += __shfl_xor_sync(0xFFFFFFFFu, ss, off);
    if ((threadIdx.x & 31) == 0) atomicAdd(&g_css[z][ch], ss);
}

// ---------------- K3: channel Gram via tensor cores + ldmatrix ----------------
__global__ void __launch_bounds__(256)
k3_gram()
{
    __shared__ __align__(16) char smraw[16896 + 12672];  // qsm[32][132] + ksm[24][132] half2
    __half2 (*qsm)[132] = reinterpret_cast<__half2(*)[132]>(smraw);
    __half2 (*ksm)[132] = reinterpret_cast<__half2(*)[132]>(smraw + 16896);
    float* red = reinterpret_cast<float*>(smraw);

    int t  = blockIdx.z;
    int bh = blockIdx.y;
    int b = bh >> 3, h = bh & 7;
    int n0 = blockIdx.x * 2048;

    int qs = (t == 0) ? 1 : 0;
    int kstream = 1 - qs;
    const __half* qb = g_qkv[qs * 8 + b]      + (size_t)(h * HD) * HW + n0;
    const __half* kb = g_qkv[kstream * 8 + b] + (size_t)(C_IN + h * HD) * HW + n0;

    const int tid  = threadIdx.x;
    const int wid  = tid >> 5;
    const int lane = tid & 31;
    const int kw = wid * 16;

    const int lg = lane >> 3;
    const int lrow = lane & 7;
    const uint32_t q_lane_off = (uint32_t)((((lg & 1) << 3) + lrow) * 132 + ((lg >> 1) << 2)) * 4;
    const uint32_t k_lane_off = (uint32_t)(((lane & 15) & 7) * 132 + (((lane & 15) >> 3) << 2)) * 4;
    const uint32_t qbase = sh_addr(&qsm[0][0]);
    const uint32_t kbase = sh_addr(&ksm[0][0]);

    float acc[2][3][4];
#pragma unroll
    for (int i = 0; i < 2; i++)
#pragma unroll
        for (int j = 0; j < 3; j++)
#pragma unroll
            for (int q = 0; q < 4; q++) acc[i][j][q] = 0.f;

    for (int c0 = 0; c0 < 2048; c0 += 256) {
        __syncthreads();
        for (int i = tid; i < 1536; i += 256) {
            int arr = (i >= 768);
            int li  = arr ? (i - 768) : i;
            int row = li >> 5;
            int v8  = (li & 31) * 8;
            const __half* src = arr ? kb : qb;
            uint4 v = *(const uint4*)&src[(size_t)row * HW + c0 + v8];
            if (arr) *(uint4*)&ksm[row][v8 >> 1] = v;
            else     *(uint4*)&qsm[row][v8 >> 1] = v;
        }
        __syncthreads();
#pragma unroll
        for (int kst = 0; kst < 2; kst++) {
            const int ko = kw + kst * 8;
            uint32_t afr[2][4];
#pragma unroll
            for (int mt = 0; mt < 2; mt++)
                ldmx4(afr[mt], qbase + q_lane_off + (uint32_t)((mt * 16 * 132 + ko) * 4));
#pragma unroll
            for (int nt = 0; nt < 3; nt++) {
                uint32_t bfr[2];
                ldmx2(bfr, kbase + k_lane_off + (uint32_t)((nt * 8 * 132 + ko) * 4));
#pragma unroll
                for (int mt = 0; mt < 2; mt++)
                    mma_16x8x16(acc[mt][nt], afr[mt], bfr);
            }
        }
    }
    __syncthreads();

    const int lr = lane >> 2;
    const int lc = lane & 3;
    float* rw = red + wid * 576;
#pragma unroll
    for (int mt = 0; mt < 2; mt++) {
        int r0 = mt * 16 + lr;
#pragma unroll
        for (int nt = 0; nt < 3; nt++) {
            int cc = nt * 8 + lc * 2;
            rw[r0 * 24 + cc]     = acc[mt][nt][0];
            rw[r0 * 24 + cc + 1] = acc[mt][nt][1];
            if (mt == 0) {
                rw[(r0 + 8) * 24 + cc]     = acc[mt][nt][2];
                rw[(r0 + 8) * 24 + cc + 1] = acc[mt][nt][3];
            }
        }
    }
    __syncthreads();

    float* Sp = &g_S[t][b][h][0];
    for (int i = tid; i < 576; i += 256) {
        float s = 0.f;
#pragma unroll
        for (int w = 0; w < 8; w++) s += red[w * 576 + i];
        atomicAdd(&Sp[i], s);
    }
}

// ---------------- K4: scale + softmax + M = wproj @ blockdiag(attn), fp16 out ----------------
__global__ void k4_softmax_M(const float* __restrict__ wproj,
                             const float* __restrict__ temp)
{
    int t = blockIdx.x >> 3, b = blockIdx.x & 7;
    int qs = (t == 0) ? 1 : 0;
    int kstream = 1 - qs;
    __shared__ float attn[C_IN][HD + 1];
    __shared__ float invq[C_IN], invk[C_IN];

    int tid = threadIdx.x;                 // 192 ; tid = h*HD + c
    {
        invq[tid] = 1.f / fmaxf(sqrtf(g_css[qs * 8 + b][tid]), 1e-12f);
        invk[tid] = 1.f / fmaxf(sqrtf(g_css[kstream * 8 + b][C_IN + tid]), 1e-12f);
    }
    __syncthreads();
    {
        int h = tid / HD, c = tid % HD;
        float tp = temp[h];
        float iq = invq[tid];
        float row[HD];
        float mx = -1e30f;
#pragma unroll
        for (int d = 0; d < HD; d++) {
            float v = g_S[t][b][h][c * HD + d] * iq * invk[h * HD + d] * tp;
            row[d] = v;
            mx = fmaxf(mx, v);
        }
        float sum = 0.f;
#pragma unroll
        for (int d = 0; d < HD; d++) { row[d] = expf(row[d] - mx); sum += row[d]; }
        float inv = 1.f / sum;
#pragma unroll
        for (int d = 0; d < HD; d++) attn[tid][d] = row[d] * inv;
    }
    __syncthreads();

    int o = tid;
    const float* wp = wproj + (size_t)o * C_IN;
    __half* Mrow = &g_M[t][b][(size_t)o * C_IN];
    for (int h = 0; h < HEADS; h++) {
        float wreg[HD];
#pragma unroll
        for (int i = 0; i < HD; i++) wreg[i] = wp[h * HD + i];
#pragma unroll
        for (int j = 0; j < HD; j++) {
            float s = 0.f;
#pragma unroll
            for (int i = 0; i < HD; i++) s += wreg[i] * attn[h * HD + i][j];
            Mrow[h * HD + j] = __float2half(s);
        }
    }
}

// ---------------- launch ----------------
extern "C" void kernel_launch(void* const* d_in, const int* in_sizes, int n_in,
                              void* d_out, int out_size)
{
    const float* rgb   = (const float*)d_in[0];
    const float* ir    = (const float*)d_in[1];
    const float* wqkv  = (const float*)d_in[2];
    const float* wdw   = (const float*)d_in[3];
    const float* wproj = (const float*)d_in[4];
    const float* temp  = (const float*)d_in[5];
    float* out = (float*)d_out;

    k0_zero<<<432, 256>>>(wqkv);
    k_nop1<<<1, 32>>>();     // keep ncu's profiled slot on k1_qkv
    k_nop2<<<1, 32>>>();

    dim3 g1(HW / 64, 3, 16);      // n0: 64-wide tiles; m0: 0,192,384
    k1_qkv<<<g1, 256>>>(rgb, ir);

    dim3 g2(HW / 2048, C3, 16);
    k2_dw<<<g2, 256>>>(wdw);

    dim3 g3(8, NB * HEADS, 2);    // K-slices of 2048
    k3_gram<<<g3, 256>>>();

    k4_softmax_M<<<16, 192>>>(wproj, temp);

    dim3 g5(HW / 64, 1, 16);      // single m pass (192 rows)
    k5_out<<<g5, 256>>>(out);
}

// round 13
// speedup vs baseline: 1.1937x; 1.1022x over previous
#include <cuda_runtime.h>
#include <cuda_fp16.h>
#include <cstdint>
#include <math.h>

// ---------------- problem constants ----------------
#define HW     16384      // 128*128
#define WIMG   128
#define C_IN   192
#define C3     576        // 3*C_IN
#define NB     8
#define HEADS  8
#define HD     24

// ---------------- scratch ----------------
__device__ __align__(16) __half g_y  [16][C3 * HW];
__device__ __align__(16) __half g_qkv[16][C3 * HW];
__device__ __align__(16) __half g_wh [C3 * C_IN];          // wqkv fp16
__device__ float  g_S  [2][NB][HEADS][HD * HD];
__device__ float  g_css[16][C3];
__device__ __align__(16) __half g_M  [2][NB][C_IN * C_IN]; // fused proj, fp16

// ---------------- K0: zero accumulators + convert weights ----------------
__global__ void k0_zero(const float* __restrict__ wqkv) {
    int idx = blockIdx.x * 256 + threadIdx.x;
    const int nS = 2 * NB * HEADS * HD * HD;
    const int nC = 16 * C3;
    if (idx < nS) (&g_S[0][0][0][0])[idx] = 0.f;
    if (idx < nC) (&g_css[0][0])[idx] = 0.f;
    if (idx < C3 * C_IN) g_wh[idx] = __float2half(wqkv[idx]);
}

// no-op shims so ncu's fixed skip-count lands on k1_qkv
__global__ void k_nop1() {}
__global__ void k_nop2() {}

// ---------------- fp16 / mma / async helpers ----------------
__device__ __forceinline__ uint32_t pack2(float a, float b) {
    __half2 h = __floats2half2_rn(a, b);
    return *(uint32_t*)&h;
}
__device__ __forceinline__ void mma_16x8x16(float* c, const uint32_t* a, const uint32_t* b) {
    asm volatile(
        "mma.sync.aligned.m16n8k16.row.col.f32.f16.f16.f32 "
        "{%0,%1,%2,%3}, {%4,%5,%6,%7}, {%8,%9}, {%0,%1,%2,%3};"
        : "+f"(c[0]), "+f"(c[1]), "+f"(c[2]), "+f"(c[3])
        : "r"(a[0]), "r"(a[1]), "r"(a[2]), "r"(a[3]), "r"(b[0]), "r"(b[1]));
}
__device__ __forceinline__ void ldmx4(uint32_t* r, uint32_t addr) {
    asm volatile("ldmatrix.sync.aligned.m8n8.x4.shared.b16 {%0,%1,%2,%3}, [%4];"
        : "=r"(r[0]), "=r"(r[1]), "=r"(r[2]), "=r"(r[3]) : "r"(addr));
}
__device__ __forceinline__ void ldmx4t(uint32_t* r, uint32_t addr) {
    asm volatile("ldmatrix.sync.aligned.m8n8.x4.trans.shared.b16 {%0,%1,%2,%3}, [%4];"
        : "=r"(r[0]), "=r"(r[1]), "=r"(r[2]), "=r"(r[3]) : "r"(addr));
}
__device__ __forceinline__ void ldmx2(uint32_t* r, uint32_t addr) {
    asm volatile("ldmatrix.sync.aligned.m8n8.x2.shared.b16 {%0,%1}, [%2];"
        : "=r"(r[0]), "=r"(r[1]) : "r"(addr));
}
__device__ __forceinline__ uint32_t sh_addr(const void* p) {
    return (uint32_t)__cvta_generic_to_shared(p);
}
__device__ __forceinline__ void cp_async16(uint32_t dst, const void* src) {
    asm volatile("cp.async.cg.shared.global [%0], [%1], 16;" :: "r"(dst), "l"(src));
}
#define CP_COMMIT() asm volatile("cp.async.commit_group;" ::: "memory")
#define CP_WAIT0()  asm volatile("cp.async.wait_group 0;"  ::: "memory")

// ---------------- fp16 mma GEMM: C[m0:m0+192, n0:n0+64] = A(.,192)@B(192,HW) ----------------
// 256 threads, 8 warps (4M x 2N), warp tile 48x32. BK=32, double-buffered, 6 chunks.
// A (fp16) staged via 16B cp.async. B: fp16 -> 16B cp.async; fp32 -> convert + STS.64.
template<bool B_HALF, bool C_HALF>
__device__ __forceinline__ void gemm_mma_192x64(
    const __half* __restrict__ A, const void* __restrict__ Bv, void* __restrict__ Cv,
    int m0, int n0)
{
    __shared__ uint32_t As[2][192][20];   // [m][k2]  30720 B (row stride 80B, 16B-mult)
    __shared__ uint32_t Bs[2][32][36];    // [k][n words], stride 144B  9216 B

    const int tid  = threadIdx.x;
    const int wid  = tid >> 5;
    const int lane = tid & 31;
    const int warp_m = wid & 3;           // 0..3 -> 48 rows
    const int warp_n = wid >> 2;          // 0..1 -> 32 cols
    const int lr = lane >> 2;
    const int lc = lane & 3;

    // A staging (16B): row = (tid>>2) + it*64, qw = (tid&3)*4 words
    const int ar16 = tid >> 2;            // 0..63
    const int aq16 = tid & 3;             // 0..3 -> 8 halves each
    // B fp16 staging (16B): row = tid>>3 (0..31), 8-half group (tid&7)
    const int bhr = tid >> 3;
    const int bhq = tid & 7;
    // B fp32 staging: bk row, bn4 halves
    const int bk = tid >> 4;              // 0..15 -> rows bk, bk+16
    const int bn4 = (tid & 15) * 4;

    const __half* Ap = A + (size_t)(m0 + ar16) * 192 + aq16 * 8;
    const float*  Bpf = B_HALF ? nullptr : ((const float*)Bv + (size_t)bk * HW + n0 + bn4);
    const __half* Bph = B_HALF ? ((const __half*)Bv + (size_t)bhr * HW + n0 + bhq * 8) : nullptr;

    // fragment lane offsets
    const int lg = lane >> 3;
    const int lrow = lane & 7;
    const uint32_t a_lane_off = (uint32_t)((((lg & 1) << 3) + lrow) * 20 + ((lg >> 1) << 2)) * 4;
    const int bj = lane >> 3;
    const uint32_t b_lane_off =
        (uint32_t)((((bj & 1) << 3) + lrow) * 36 + ((bj >> 1) << 2) + warp_n * 16) * 4;

    const uint32_t As0 = sh_addr(&As[0][0][0]);
    const uint32_t As1 = sh_addr(&As[1][0][0]);
    const uint32_t Bs0 = sh_addr(&Bs[0][0][0]);
    const uint32_t Bs1 = sh_addr(&Bs[1][0][0]);

    const uint32_t asdst0 = As0 + (uint32_t)((ar16 * 20 + aq16 * 4) * 4);
    const uint32_t asdst1 = As1 + (uint32_t)((ar16 * 20 + aq16 * 4) * 4);
    const uint32_t bsdst0 = Bs0 + (uint32_t)((bhr * 36 + bhq * 4) * 4);
    const uint32_t bsdst1 = Bs1 + (uint32_t)((bhr * 36 + bhq * 4) * 4);

    uint2 bu[2];   // fp32-B path only

    auto stageA = [&](int nb, int ch) {
        const __half* src = Ap + ch * 32;
        uint32_t dst = nb ? asdst1 : asdst0;
#pragma unroll
        for (int it = 0; it < 3; it++)
            cp_async16(dst + (uint32_t)(it * 64 * 20 * 4), src + (size_t)it * 64 * 192);
    };
    auto stageB_async = [&](int nb, int ch) {
        uint32_t dst = nb ? bsdst1 : bsdst0;
        cp_async16(dst, Bph + (size_t)(ch * 32) * HW);
    };
    auto loadB = [&](int ch) {
#pragma unroll
        for (int p = 0; p < 2; p++) {
            float4 v = *(const float4*)(Bpf + (size_t)(ch * 32 + p * 16) * HW);
            bu[p].x = pack2(v.x, v.y);
            bu[p].y = pack2(v.z, v.w);
        }
    };
    auto stsB = [&](int nb) {
#pragma unroll
        for (int p = 0; p < 2; p++)
            *(uint2*)&Bs[nb][bk + p * 16][bn4 >> 1] = bu[p];
    };

    // prologue
    stageA(0, 0);
    if (B_HALF) stageB_async(0, 0);
    else { loadB(0); stsB(0); }
    CP_COMMIT();
    CP_WAIT0();
    __syncthreads();

    float acc[3][4][4];
#pragma unroll
    for (int i = 0; i < 3; i++)
#pragma unroll
        for (int j = 0; j < 4; j++)
#pragma unroll
            for (int q = 0; q < 4; q++) acc[i][j][q] = 0.f;

    int buf = 0;
    for (int ch = 0; ch < 6; ch++) {
        int nb = buf ^ 1;
        if (ch < 5) {
            stageA(nb, ch + 1);
            if (B_HALF) stageB_async(nb, ch + 1);
            CP_COMMIT();
            if (!B_HALF) loadB(ch + 1);
        }
        const uint32_t Asb = (buf ? As1 : As0) + a_lane_off;
        const uint32_t Bsb = (buf ? Bs1 : Bs0) + b_lane_off;
#pragma unroll
        for (int kst = 0; kst < 2; kst++) {
            uint32_t afr[3][4];
#pragma unroll
            for (int mt = 0; mt < 3; mt++)
                ldmx4(afr[mt], Asb + (uint32_t)(((warp_m * 48 + mt * 16) * 20 + kst * 8) * 4));
#pragma unroll
            for (int ntp = 0; ntp < 2; ntp++) {
                uint32_t bfr4[4];
                ldmx4t(bfr4, Bsb + (uint32_t)((kst * 16 * 36 + ntp * 8) * 4));
#pragma unroll
                for (int mt = 0; mt < 3; mt++) {
                    mma_16x8x16(acc[mt][ntp * 2],     afr[mt], &bfr4[0]);
                    mma_16x8x16(acc[mt][ntp * 2 + 1], afr[mt], &bfr4[2]);
                }
            }
        }
        if (ch < 5) {
            if (!B_HALF) stsB(nb);
            CP_WAIT0();
            __syncthreads();
            buf = nb;
        }
    }

#pragma unroll
    for (int mt = 0; mt < 3; mt++) {
        int row = m0 + warp_m * 48 + mt * 16 + lr;
#pragma unroll
        for (int nt = 0; nt < 4; nt++) {
            int col = n0 + warp_n * 32 + nt * 8 + lc * 2;
            if (C_HALF) {
                __half* Ch = (__half*)Cv;
                *(uint32_t*)(Ch + (size_t)row * HW + col)       = pack2(acc[mt][nt][0], acc[mt][nt][1]);
                *(uint32_t*)(Ch + (size_t)(row + 8) * HW + col) = pack2(acc[mt][nt][2], acc[mt][nt][3]);
            } else {
                float* Cf = (float*)Cv;
                *(float2*)(Cf + (size_t)row * HW + col)       = make_float2(acc[mt][nt][0], acc[mt][nt][1]);
                *(float2*)(Cf + (size_t)(row + 8) * HW + col) = make_float2(acc[mt][nt][2], acc[mt][nt][3]);
            }
        }
    }
}

// ---------------- K1: 1x1 qkv conv ----------------
__global__ void __launch_bounds__(256, 2)
k1_qkv(const float* __restrict__ rgb, const float* __restrict__ ir)
{
    int z = blockIdx.z, s = z >> 3, b = z & 7;
    const float* x = (s ? ir : rgb) + (size_t)b * C_IN * HW;
    gemm_mma_192x64<false, true>(g_wh, x, g_y[z], blockIdx.y * 192, blockIdx.x * 64);
}

// ---------------- K5: out = M @ V ----------------
__global__ void __launch_bounds__(256, 2)
k5_out(float* __restrict__ out)
{
    int z = blockIdx.z;
    const __half* A = g_M[z >> 3][z & 7];
    const __half* V = g_qkv[z] + (size_t)(2 * C_IN) * HW;
    float* C = out + (size_t)z * C_IN * HW;
    gemm_mma_192x64<true, false>(A, V, C, 0, blockIdx.x * 64);
}

// ---------------- K2: depthwise 3x3 SAME, 8 cols x 4 rows per thread + sumsq ----------------
// Block: 256 threads covering 64 rows x 128 cols of one (z,ch). Grid (2, C3, 16).
// Read amplification 1.5x (6 rows loaded per 4 written) vs 3x before.
__global__ void k2_dw(const float* __restrict__ wdw)
{
    int z  = blockIdx.z;
    int ch = blockIdx.y;
    const __half* yin = g_y[z]  + (size_t)ch * HW;
    __half*       out = g_qkv[z] + (size_t)ch * HW;

    const float* w = wdw + ch * 9;
    float wr[3][3];
#pragma unroll
    for (int i = 0; i < 9; i++) wr[i / 3][i % 3] = w[i];

    int t = threadIdx.x;
    int xx = (t & 15) * 8;
    int row0 = blockIdx.x * 64 + (t >> 4) * 4;   // 4 output rows: row0..row0+3
    bool xm = (xx > 0), xp = (xx < 120);

    float f[6][10];
#pragma unroll
    for (int r = 0; r < 6; r++) {
        int ry = row0 - 1 + r;
        if (ry < 0 || ry >= WIMG) {
#pragma unroll
            for (int i = 0; i < 10; i++) f[r][i] = 0.f;
            continue;
        }
        const __half* rp = yin + (size_t)ry * WIMG;
        uint4 v = *(const uint4*)&rp[xx];
        float2 p0 = __half22float2(*(__half2*)&v.x);
        float2 p1 = __half22float2(*(__half2*)&v.y);
        float2 p2 = __half22float2(*(__half2*)&v.z);
        float2 p3 = __half22float2(*(__half2*)&v.w);
        f[r][1] = p0.x; f[r][2] = p0.y; f[r][3] = p1.x; f[r][4] = p1.y;
        f[r][5] = p2.x; f[r][6] = p2.y; f[r][7] = p3.x; f[r][8] = p3.y;
        f[r][0] = xm ? __half2float(rp[xx - 1]) : 0.f;
        f[r][9] = xp ? __half2float(rp[xx + 8]) : 0.f;
    }

    float ss = 0.f;
#pragma unroll
    for (int r = 0; r < 4; r++) {
        float o[8];
#pragma unroll
        for (int i = 0; i < 8; i++) {
            float acc = 0.f;
#pragma unroll
            for (int dr = 0; dr < 3; dr++)
                acc += wr[dr][0] * f[r + dr][i] + wr[dr][1] * f[r + dr][i + 1]
                     + wr[dr][2] * f[r + dr][i + 2];
            o[i] = acc;
            ss += acc * acc;
        }
        uint4 ov;
        ov.x = pack2(o[0], o[1]);
        ov.y = pack2(o[2], o[3]);
        ov.z = pack2(o[4], o[5]);
        ov.w = pack2(o[6], o[7]);
        *(uint4*)&out[(size_t)(row0 + r) * WIMG + xx] = ov;
    }

#pragma unroll
    for (int off = 16; off; off >>= 1) ss += __shfl_xor_sync(0xFFFFFFFFu, ss, off);
    if ((threadIdx.x & 31) == 0) atomicAdd(&g_css[z][ch], ss);
}

// ---------------- K3: channel Gram via tensor cores + ldmatrix ----------------
__global__ void __launch_bounds__(256)
k3_gram()
{
    __shared__ __align__(16) char smraw[16896 + 12672];  // qsm[32][132] + ksm[24][132] half2
    __half2 (*qsm)[132] = reinterpret_cast<__half2(*)[132]>(smraw);
    __half2 (*ksm)[132] = reinterpret_cast<__half2(*)[132]>(smraw + 16896);
    float* red = reinterpret_cast<float*>(smraw);

    int t  = blockIdx.z;
    int bh = blockIdx.y;
    int b = bh >> 3, h = bh & 7;
    int n0 = blockIdx.x * 2048;

    int qs = (t == 0) ? 1 : 0;
    int kstream = 1 - qs;
    const __half* qb = g_qkv[qs * 8 + b]      + (size_t)(h * HD) * HW + n0;
    const __half* kb = g_qkv[kstream * 8 + b] + (size_t)(C_IN + h * HD) * HW + n0;

    const int tid  = threadIdx.x;
    const int wid  = tid >> 5;
    const int lane = tid & 31;
    const int kw = wid * 16;

    const int lg = lane >> 3;
    const int lrow = lane & 7;
    const uint32_t q_lane_off = (uint32_t)((((lg & 1) << 3) + lrow) * 132 + ((lg >> 1) << 2)) * 4;
    const uint32_t k_lane_off = (uint32_t)(((lane & 15) & 7) * 132 + (((lane & 15) >> 3) << 2)) * 4;
    const uint32_t qbase = sh_addr(&qsm[0][0]);
    const uint32_t kbase = sh_addr(&ksm[0][0]);

    float acc[2][3][4];
#pragma unroll
    for (int i = 0; i < 2; i++)
#pragma unroll
        for (int j = 0; j < 3; j++)
#pragma unroll
            for (int q = 0; q < 4; q++) acc[i][j][q] = 0.f;

    for (int c0 = 0; c0 < 2048; c0 += 256) {
        __syncthreads();
        for (int i = tid; i < 1536; i += 256) {
            int arr = (i >= 768);
            int li  = arr ? (i - 768) : i;
            int row = li >> 5;
            int v8  = (li & 31) * 8;
            const __half* src = arr ? kb : qb;
            uint4 v = *(const uint4*)&src[(size_t)row * HW + c0 + v8];
            if (arr) *(uint4*)&ksm[row][v8 >> 1] = v;
            else     *(uint4*)&qsm[row][v8 >> 1] = v;
        }
        __syncthreads();
#pragma unroll
        for (int kst = 0; kst < 2; kst++) {
            const int ko = kw + kst * 8;
            uint32_t afr[2][4];
#pragma unroll
            for (int mt = 0; mt < 2; mt++)
                ldmx4(afr[mt], qbase + q_lane_off + (uint32_t)((mt * 16 * 132 + ko) * 4));
#pragma unroll
            for (int nt = 0; nt < 3; nt++) {
                uint32_t bfr[2];
                ldmx2(bfr, kbase + k_lane_off + (uint32_t)((nt * 8 * 132 + ko) * 4));
#pragma unroll
                for (int mt = 0; mt < 2; mt++)
                    mma_16x8x16(acc[mt][nt], afr[mt], bfr);
            }
        }
    }
    __syncthreads();

    const int lr = lane >> 2;
    const int lc = lane & 3;
    float* rw = red + wid * 576;
#pragma unroll
    for (int mt = 0; mt < 2; mt++) {
        int r0 = mt * 16 + lr;
#pragma unroll
        for (int nt = 0; nt < 3; nt++) {
            int cc = nt * 8 + lc * 2;
            rw[r0 * 24 + cc]     = acc[mt][nt][0];
            rw[r0 * 24 + cc + 1] = acc[mt][nt][1];
            if (mt == 0) {
                rw[(r0 + 8) * 24 + cc]     = acc[mt][nt][2];
                rw[(r0 + 8) * 24 + cc + 1] = acc[mt][nt][3];
            }
        }
    }
    __syncthreads();

    float* Sp = &g_S[t][b][h][0];
    for (int i = tid; i < 576; i += 256) {
        float s = 0.f;
#pragma unroll
        for (int w = 0; w < 8; w++) s += red[w * 576 + i];
        atomicAdd(&Sp[i], s);
    }
}

// ---------------- K4: scale + softmax + M = wproj @ blockdiag(attn), fp16 out ----------------
__global__ void k4_softmax_M(const float* __restrict__ wproj,
                             const float* __restrict__ temp)
{
    int t = blockIdx.x >> 3, b = blockIdx.x & 7;
    int qs = (t == 0) ? 1 : 0;
    int kstream = 1 - qs;
    __shared__ float attn[C_IN][HD + 1];
    __shared__ float invq[C_IN], invk[C_IN];

    int tid = threadIdx.x;                 // 192 ; tid = h*HD + c
    {
        invq[tid] = 1.f / fmaxf(sqrtf(g_css[qs * 8 + b][tid]), 1e-12f);
        invk[tid] = 1.f / fmaxf(sqrtf(g_css[kstream * 8 + b][C_IN + tid]), 1e-12f);
    }
    __syncthreads();
    {
        int h = tid / HD, c = tid % HD;
        float tp = temp[h];
        float iq = invq[tid];
        float row[HD];
        float mx = -1e30f;
#pragma unroll
        for (int d = 0; d < HD; d++) {
            float v = g_S[t][b][h][c * HD + d] * iq * invk[h * HD + d] * tp;
            row[d] = v;
            mx = fmaxf(mx, v);
        }
        float sum = 0.f;
#pragma unroll
        for (int d = 0; d < HD; d++) { row[d] = expf(row[d] - mx); sum += row[d]; }
        float inv = 1.f / sum;
#pragma unroll
        for (int d = 0; d < HD; d++) attn[tid][d] = row[d] * inv;
    }
    __syncthreads();

    int o = tid;
    const float* wp = wproj + (size_t)o * C_IN;
    __half* Mrow = &g_M[t][b][(size_t)o * C_IN];
    for (int h = 0; h < HEADS; h++) {
        float wreg[HD];
#pragma unroll
        for (int i = 0; i < HD; i++) wreg[i] = wp[h * HD + i];
#pragma unroll
        for (int j = 0; j < HD; j++) {
            float s = 0.f;
#pragma unroll
            for (int i = 0; i < HD; i++) s += wreg[i] * attn[h * HD + i][j];
            Mrow[h * HD + j] = __float2half(s);
        }
    }
}

// ---------------- launch ----------------
extern "C" void kernel_launch(void* const* d_in, const int* in_sizes, int n_in,
                              void* d_out, int out_size)
{
    const float* rgb   = (const float*)d_in[0];
    const float* ir    = (const float*)d_in[1];
    const float* wqkv  = (const float*)d_in[2];
    const float* wdw   = (const float*)d_in[3];
    const float* wproj = (const float*)d_in[4];
    const float* temp  = (const float*)d_in[5];
    float* out = (float*)d_out;

    k0_zero<<<432, 256>>>(wqkv);
    k_nop1<<<1, 32>>>();     // keep ncu's profiled slot on k1_qkv
    k_nop2<<<1, 32>>>();

    dim3 g1(HW / 64, 3, 16);      // n0: 64-wide tiles; m0: 0,192,384
    k1_qkv<<<g1, 256>>>(rgb, ir);

    dim3 g2(2, C3, 16);           // 64 rows x 128 cols per block
    k2_dw<<<g2, 256>>>(wdw);

    dim3 g3(8, NB * HEADS, 2);    // K-slices of 2048
    k3_gram<<<g3, 256>>>();

    k4_softmax_M<<<16, 192>>>(wproj, temp);

    dim3 g5(HW / 64, 1, 16);      // single m pass (192 rows)
    k5_out<<<g5, 256>>>(out);
}